// round 2
// baseline (speedup 1.0000x reference)
#include <cuda_runtime.h>
#include <math.h>

#define NB 16
#define NC 32
#define NT 13
#define NN 2000
#define NK 20
#define ND (NT*NC)      // 416
#define BT (NB*NT)      // 208
#define CH 8            // channels per prop chunk
#define NCHUNK (NC/CH)  // 4
#define SPITCH 2001     // padded smem row pitch (floats)

// ---------------- scratch (device globals; no allocation allowed) ----------------
__device__ float g_h2[(size_t)BT*NC*NN];   // h after 2 prop steps, [bt][c][n]
__device__ float g_left[NB*NN];
__device__ float g_right[NB*NN];
__device__ int   g_idx[NN*NK];
__device__ float g_adj1v[NN*NK];
__device__ float g_Aval[NB*NN*NK];
__device__ float g_sortedR[NB*2048];
__device__ float g_sufHigh[NB*2049];
__device__ float g_cumLowEx[NB*2049];
__device__ float g_u1[ND];
__device__ float g_u2[ND];
__device__ float g_LR0[2];

// ---------------- kernel 1: adj relu + row-normalize + top-K (warp per row) ----------------
__global__ void k_adj(const float* __restrict__ adj) {
    __shared__ float sv[4 * NN];
    int warp = threadIdx.x >> 5, lane = threadIdx.x & 31;
    int row = blockIdx.x * 4 + warp;
    if (row >= NN) return;
    float* v = sv + warp * NN;
    const float* arow = adj + (size_t)row * NN;

    float psum = 0.f;
    float bv = -1.f; int bi = 0;
#pragma unroll 8
    for (int q = 0; q < 63; q++) {
        int e = lane + 32 * q;
        if (e < NN) {
            float xv = arow[e];
            xv = xv > 0.f ? xv : 0.f;
            v[e] = xv;
            psum += xv;
            if (xv > bv) { bv = xv; bi = e; }
        }
    }
#pragma unroll
    for (int o = 16; o > 0; o >>= 1) psum += __shfl_xor_sync(0xffffffffu, psum, o);
    float invdeg = 1.0f / psum;

    for (int it = 0; it < NK; it++) {
        float mv = bv; int mi = bi;
#pragma unroll
        for (int o = 16; o > 0; o >>= 1) {
            float ov = __shfl_xor_sync(0xffffffffu, mv, o);
            int   oi = __shfl_xor_sync(0xffffffffu, mi, o);
            if (ov > mv || (ov == mv && oi < mi)) { mv = ov; mi = oi; }
        }
        if (lane == 0) {
            g_idx[row * NK + it] = mi;
            g_adj1v[row * NK + it] = mv * invdeg;
        }
        // winner lane removes the element and rescans its strided slice
        if ((mi & 31) == lane) {
            v[mi] = -2.0f;
            bv = -1.f; bi = 0;
#pragma unroll 8
            for (int q = 0; q < 63; q++) {
                int e = lane + 32 * q;
                if (e < NN) {
                    float xv = v[e];
                    if (xv > bv) { bv = xv; bi = e; }
                }
            }
        }
        __syncwarp();
    }
}

// ---------------- kernel 2: u1/u2 = a-slices folded into W2; bias constants ----------------
__global__ void k_u(const float* __restrict__ W2, const float* __restrict__ b2,
                    const float* __restrict__ a) {
    int tid = threadIdx.x;
    if (tid < ND) {
        int t = tid >> 5, c = tid & 31;
        float s1 = 0.f, s2 = 0.f;
        for (int o = 0; o < NC; o++) {
            float w = W2[o * NC + c];
            s1 += a[t * NC + o] * w;
            s2 += a[ND + t * NC + o] * w;
        }
        g_u1[tid] = s1;
        g_u2[tid] = s2;
    } else if (tid == ND) {
        float s = 0.f;
        for (int d = 0; d < ND; d++) s += b2[d & 31] * a[d];
        g_LR0[0] = s;
    } else if (tid == ND + 1) {
        float s = 0.f;
        for (int d = 0; d < ND; d++) s += b2[d & 31] * a[ND + d];
        g_LR0[1] = s;
    }
}

// ---------------- kernel 3: left/right directly from x (thread = node) ----------------
__global__ void k_lr(const float* __restrict__ x) {
    __shared__ float su1[ND], su2[ND];
    int tid = threadIdx.x;
    for (int i = tid; i < ND; i += 256) { su1[i] = g_u1[i]; su2[i] = g_u2[i]; }
    __syncthreads();
    int n = blockIdx.x * 256 + tid;
    int b = blockIdx.y;
    if (n >= NN) return;
    const float* xb = x + (size_t)b * NC * NT * NN + n;
    float s1 = 0.f, s2 = 0.f;
#pragma unroll 4
    for (int c = 0; c < NC; c++) {
#pragma unroll
        for (int t = 0; t < NT; t++) {
            float v = xb[(size_t)(c * NT + t) * NN];
            s1 += v * su1[t * NC + c];
            s2 += v * su2[t * NC + c];
        }
    }
    g_left[b * NN + n]  = s1 + g_LR0[0];
    g_right[b * NN + n] = s2 + g_LR0[1];
}

// ---------------- kernel 4: per-batch sort of right + prefix/suffix exp-sums ----------------
__global__ void k_sort() {
    __shared__ float ss[2048];
    __shared__ float sl[2048];
    __shared__ float sh[2048];
    int b = blockIdx.x;
    int tid = threadIdx.x;

    for (int e = tid; e < 2048; e += 1024)
        ss[e] = (e < NN) ? g_right[b * NN + e] : INFINITY;
    __syncthreads();

    for (int k2 = 2; k2 <= 2048; k2 <<= 1) {
        for (int j = k2 >> 1; j > 0; j >>= 1) {
            for (int e = tid; e < 2048; e += 1024) {
                int p = e ^ j;
                if (p > e) {
                    bool up = ((e & k2) == 0);
                    float av = ss[e], bvv = ss[p];
                    if ((av > bvv) == up) { ss[e] = bvv; ss[p] = av; }
                }
            }
            __syncthreads();
        }
    }

    for (int e = tid; e < 2048; e += 1024) {
        sl[e] = (e < NN) ? expf(0.2f * ss[e]) : 0.f;
        sh[e] = (e < NN) ? expf(ss[e]) : 0.f;
    }
    __syncthreads();

    for (int off = 1; off < 2048; off <<= 1) {
        int e0 = tid, e1 = tid + 1024;
        float l0 = sl[e0] + ((e0 >= off) ? sl[e0 - off] : 0.f);
        float l1 = sl[e1] + ((e1 >= off) ? sl[e1 - off] : 0.f);
        float h0 = sh[e0] + ((e0 + off < 2048) ? sh[e0 + off] : 0.f);
        float h1 = sh[e1] + ((e1 + off < 2048) ? sh[e1 + off] : 0.f);
        __syncthreads();
        sl[e0] = l0; sl[e1] = l1;
        sh[e0] = h0; sh[e1] = h1;
        __syncthreads();
    }

    for (int e = tid; e < 2048; e += 1024) {
        g_sortedR[b * 2048 + e] = ss[e];
        g_cumLowEx[b * 2049 + e + 1] = sl[e];
        g_sufHigh[b * 2049 + e] = sh[e];
    }
    if (tid == 0) {
        g_cumLowEx[b * 2049] = 0.f;
        g_sufHigh[b * 2049 + 2048] = 0.f;
    }
}

// ---------------- kernel 5: A values at the K sparse slots ----------------
__global__ void k_aval() {
    int g = blockIdx.x * blockDim.x + threadIdx.x;
    if (g >= NB * NN) return;
    int b = g / NN, i = g - b * NN;
    float l = g_left[g];
    float theta = -l;
    const float* sr = g_sortedR + b * 2048;
    int lo = 0, hi = 2048;
    while (lo < hi) {
        int mid = (lo + hi) >> 1;
        if (sr[mid] < theta) lo = mid + 1; else hi = mid;
    }
    int pos = lo;
    float denom = expf(l) * g_sufHigh[b * 2049 + pos]
                + expf(0.2f * l) * g_cumLowEx[b * 2049 + pos];
    float inv = 1.0f / denom;
#pragma unroll
    for (int k = 0; k < NK; k++) {
        int j = g_idx[i * NK + k];
        float s = l + g_right[b * NN + j];
        float num = (s >= 0.f) ? expf(s) : expf(0.2f * s);
        g_Aval[(size_t)g * NK + k] = num * inv + g_adj1v[i * NK + k];
    }
}

// ---------------- kernel 6: fused 2-step propagation, smem-resident slab ----------------
// grid (NCHUNK, BT), 1024 threads, dynamic smem = 2 * CH * SPITCH floats
__global__ void __launch_bounds__(1024, 1) k_prop(const float* __restrict__ x) {
    extern __shared__ float smem[];
    float* sx = smem;                 // CH x SPITCH : x chunk, later h2 chunk
    float* sh = smem + CH * SPITCH;   // CH x SPITCH : h1 chunk

    int tid = threadIdx.x;
    int wid = tid >> 5, lane = tid & 31;
    int c = lane & 7, kg = lane >> 3;           // lane = kg*8 + c
    int chunk = blockIdx.x;
    int bt = blockIdx.y;
    int b = bt / NT, t = bt - b * NT;
    int ch0 = chunk * CH;

    // load x chunk slab (coalesced)
    const float* xs = x + ((size_t)(b * NC + ch0) * NT + t) * NN;
#pragma unroll
    for (int cc = 0; cc < CH; cc++)
        for (int n = tid; n < NN; n += 1024)
            sx[cc * SPITCH + n] = xs[(size_t)cc * NT * NN + n];
    __syncthreads();

    const float* avb = g_Aval + (size_t)b * NN * NK;

    // ---- step 1: h1 = 0.05 x + 0.95 A x ----
    {
        int jj = 0; float aa = 0.f;
        if (lane < NK) { jj = g_idx[wid * NK + lane]; aa = avb[wid * NK + lane]; }
        for (int m = wid; m < NN; m += 32) {
            int mn = m + 32;
            int jn = 0; float an = 0.f;
            if (lane < NK && mn < NN) { jn = g_idx[mn * NK + lane]; an = avb[mn * NK + lane]; }
            float acc = 0.f;
#pragma unroll
            for (int s = 0; s < 5; s++) {
                int k = kg * 5 + s;
                int j  = __shfl_sync(0xffffffffu, jj, k);
                float a = __shfl_sync(0xffffffffu, aa, k);
                acc += a * sx[c * SPITCH + j];
            }
            acc += __shfl_xor_sync(0xffffffffu, acc, 8);
            acc += __shfl_xor_sync(0xffffffffu, acc, 16);
            float own = sx[c * SPITCH + m];
            float val = 0.05f * own + 0.95f * acc;
            if (lane < 8) sh[c * SPITCH + m] = val;
            jj = jn; aa = an;
        }
    }
    __syncthreads();

    // ---- step 2: h2 = 0.05 x + 0.95 A h1 ; overwrite sx in place ----
    {
        int jj = 0; float aa = 0.f;
        if (lane < NK) { jj = g_idx[wid * NK + lane]; aa = avb[wid * NK + lane]; }
        for (int m = wid; m < NN; m += 32) {
            int mn = m + 32;
            int jn = 0; float an = 0.f;
            if (lane < NK && mn < NN) { jn = g_idx[mn * NK + lane]; an = avb[mn * NK + lane]; }
            float acc = 0.f;
#pragma unroll
            for (int s = 0; s < 5; s++) {
                int k = kg * 5 + s;
                int j  = __shfl_sync(0xffffffffu, jj, k);
                float a = __shfl_sync(0xffffffffu, aa, k);
                acc += a * sh[c * SPITCH + j];
            }
            acc += __shfl_xor_sync(0xffffffffu, acc, 8);
            acc += __shfl_xor_sync(0xffffffffu, acc, 16);
            float own = sx[c * SPITCH + m];       // read own x, then overwrite with h2
            float val = 0.05f * own + 0.95f * acc;
            if (lane < 8) sx[c * SPITCH + m] = val;
            jj = jn; aa = an;
        }
    }
    __syncthreads();

    // write h2 chunk (coalesced)
    float* h2 = g_h2 + ((size_t)bt * NC + ch0) * NN;
#pragma unroll
    for (int cc = 0; cc < CH; cc++)
        for (int n = tid; n < NN; n += 1024)
            h2[(size_t)cc * NN + n] = sx[cc * SPITCH + n];
}

// ---------------- kernel 7: output projection ho = W1 h2 + b1 ----------------
__global__ void k_out(float* __restrict__ out, const float* __restrict__ W1,
                      const float* __restrict__ b1) {
    __shared__ float W1s[NC * NC];
    __shared__ float b1s[NC];
    int tid = threadIdx.x;
    for (int i = tid; i < NC * NC; i += 256) W1s[i] = W1[i];
    if (tid < NC) b1s[tid] = b1[tid];
    __syncthreads();
    int bt = blockIdx.y;
    int b = bt / NT, t = bt - b * NT;
    int n = blockIdx.x * 256 + tid;
    if (n >= NN) return;
    float h[NC];
#pragma unroll
    for (int cc = 0; cc < NC; cc++)
        h[cc] = g_h2[((size_t)bt * NC + cc) * NN + n];
#pragma unroll
    for (int o = 0; o < NC; o++) {
        float s = b1s[o];
#pragma unroll
        for (int cc = 0; cc < NC; cc++) s += W1s[o * NC + cc] * h[cc];
        out[((size_t)(b * NC + o) * NT + t) * NN + n] = s;
    }
}

// ---------------- launch ----------------
extern "C" void kernel_launch(void* const* d_in, const int* in_sizes, int n_in,
                              void* d_out, int out_size) {
    const float* x   = (const float*)d_in[0];
    const float* adj = (const float*)d_in[1];
    const float* W1  = (const float*)d_in[2];
    const float* b1  = (const float*)d_in[3];
    const float* W2  = (const float*)d_in[4];
    const float* b2  = (const float*)d_in[5];
    const float* a   = (const float*)d_in[6];
    float* out = (float*)d_out;

    static int smem_set = 0;
    int prop_smem = 2 * CH * SPITCH * (int)sizeof(float);   // 128064 B
    cudaFuncSetAttribute(k_prop, cudaFuncAttributeMaxDynamicSharedMemorySize, prop_smem);

    k_adj<<<(NN + 3) / 4, 128>>>(adj);
    k_u<<<1, 512>>>(W2, b2, a);
    {
        dim3 grid(8, NB);
        k_lr<<<grid, 256>>>(x);
    }
    k_sort<<<NB, 1024>>>();
    k_aval<<<(NB * NN + 255) / 256, 256>>>();
    {
        dim3 grid(NCHUNK, BT);
        k_prop<<<grid, 1024, prop_smem>>>(x);
    }
    {
        dim3 grid(8, BT);
        k_out<<<grid, 256>>>(out, W1, b1);
    }
    (void)smem_set;
}

// round 4
// speedup vs baseline: 1.0817x; 1.0817x over previous
#include <cuda_runtime.h>
#include <math.h>

#define NB 16
#define NC 32
#define NT 13
#define NN 2000
#define NK 20
#define ND (NT*NC)      // 416
#define BT (NB*NT)      // 208
#define CH 4            // channels per prop chunk (one float4)
#define NCHUNK (NC/CH)  // 8

// ---------------- scratch (device globals; no allocation allowed) ----------------
__device__ float  g_h2[(size_t)BT*NC*NN];   // h after 2 prop steps, [bt][c][n]
__device__ float  g_left[NB*NN];
__device__ float  g_right[NB*NN];
__device__ int    g_idx[NN*NK];
__device__ float  g_adj1v[NN*NK];
__device__ float2 g_pk[(size_t)NB*NN*NK];   // packed {Aval, idx bits} per (b,n,k)
__device__ float  g_sortedR[NB*2048];
__device__ float  g_sufHigh[NB*2049];
__device__ float  g_cumLowEx[NB*2049];
__device__ float  g_u1[ND];
__device__ float  g_u2[ND];
__device__ float  g_LR0[2];

// ---------------- kernel 1: adj relu + row-normalize + top-K (warp per row) ----------------
__global__ void k_adj(const float* __restrict__ adj) {
    __shared__ float sv[4 * NN];
    int warp = threadIdx.x >> 5, lane = threadIdx.x & 31;
    int row = blockIdx.x * 4 + warp;
    if (row >= NN) return;
    float* v = sv + warp * NN;
    const float* arow = adj + (size_t)row * NN;

    float psum = 0.f;
    float bv = -1.f; int bi = 0;
#pragma unroll 8
    for (int q = 0; q < 63; q++) {
        int e = lane + 32 * q;
        if (e < NN) {
            float xv = arow[e];
            xv = xv > 0.f ? xv : 0.f;
            v[e] = xv;
            psum += xv;
            if (xv > bv) { bv = xv; bi = e; }
        }
    }
#pragma unroll
    for (int o = 16; o > 0; o >>= 1) psum += __shfl_xor_sync(0xffffffffu, psum, o);
    float invdeg = 1.0f / psum;

    for (int it = 0; it < NK; it++) {
        float mv = bv; int mi = bi;
#pragma unroll
        for (int o = 16; o > 0; o >>= 1) {
            float ov = __shfl_xor_sync(0xffffffffu, mv, o);
            int   oi = __shfl_xor_sync(0xffffffffu, mi, o);
            if (ov > mv || (ov == mv && oi < mi)) { mv = ov; mi = oi; }
        }
        if (lane == 0) {
            g_idx[row * NK + it] = mi;
            g_adj1v[row * NK + it] = mv * invdeg;
        }
        if ((mi & 31) == lane) {   // winner lane removes + rescans its slice
            v[mi] = -2.0f;
            bv = -1.f; bi = 0;
#pragma unroll 8
            for (int q = 0; q < 63; q++) {
                int e = lane + 32 * q;
                if (e < NN) {
                    float xv = v[e];
                    if (xv > bv) { bv = xv; bi = e; }
                }
            }
        }
        __syncwarp();
    }
}

// ---------------- kernel 2: u1/u2 = a-slices folded into W2; bias constants ----------------
__global__ void k_u(const float* __restrict__ W2, const float* __restrict__ b2,
                    const float* __restrict__ a) {
    int tid = threadIdx.x;
    if (tid < ND) {
        int t = tid >> 5, c = tid & 31;
        float s1 = 0.f, s2 = 0.f;
        for (int o = 0; o < NC; o++) {
            float w = W2[o * NC + c];
            s1 += a[t * NC + o] * w;
            s2 += a[ND + t * NC + o] * w;
        }
        g_u1[tid] = s1;
        g_u2[tid] = s2;
    } else if (tid == ND) {
        float s = 0.f;
        for (int d = 0; d < ND; d++) s += b2[d & 31] * a[d];
        g_LR0[0] = s;
    } else if (tid == ND + 1) {
        float s = 0.f;
        for (int d = 0; d < ND; d++) s += b2[d & 31] * a[ND + d];
        g_LR0[1] = s;
    }
}

// ---------------- kernel 3: left/right directly from x (thread = node) ----------------
__global__ void k_lr(const float* __restrict__ x) {
    __shared__ float su1[ND], su2[ND];
    int tid = threadIdx.x;
    for (int i = tid; i < ND; i += 256) { su1[i] = g_u1[i]; su2[i] = g_u2[i]; }
    __syncthreads();
    int n = blockIdx.x * 256 + tid;
    int b = blockIdx.y;
    if (n >= NN) return;
    const float* xb = x + (size_t)b * NC * NT * NN + n;
    float s1 = 0.f, s2 = 0.f;
#pragma unroll 4
    for (int c = 0; c < NC; c++) {
#pragma unroll
        for (int t = 0; t < NT; t++) {
            float v = xb[(size_t)(c * NT + t) * NN];
            s1 += v * su1[t * NC + c];
            s2 += v * su2[t * NC + c];
        }
    }
    g_left[b * NN + n]  = s1 + g_LR0[0];
    g_right[b * NN + n] = s2 + g_LR0[1];
}

// ---------------- kernel 4: per-batch sort of right + prefix/suffix exp-sums ----------------
__global__ void k_sort() {
    __shared__ float ss[2048];
    __shared__ float sl[2048];
    __shared__ float sh[2048];
    int b = blockIdx.x;
    int tid = threadIdx.x;

    for (int e = tid; e < 2048; e += 1024)
        ss[e] = (e < NN) ? g_right[b * NN + e] : INFINITY;
    __syncthreads();

    for (int k2 = 2; k2 <= 2048; k2 <<= 1) {
        for (int j = k2 >> 1; j > 0; j >>= 1) {
            for (int e = tid; e < 2048; e += 1024) {
                int p = e ^ j;
                if (p > e) {
                    bool up = ((e & k2) == 0);
                    float av = ss[e], bvv = ss[p];
                    if ((av > bvv) == up) { ss[e] = bvv; ss[p] = av; }
                }
            }
            __syncthreads();
        }
    }

    for (int e = tid; e < 2048; e += 1024) {
        sl[e] = (e < NN) ? expf(0.2f * ss[e]) : 0.f;
        sh[e] = (e < NN) ? expf(ss[e]) : 0.f;
    }
    __syncthreads();

    for (int off = 1; off < 2048; off <<= 1) {
        int e0 = tid, e1 = tid + 1024;
        float l0 = sl[e0] + ((e0 >= off) ? sl[e0 - off] : 0.f);
        float l1 = sl[e1] + ((e1 >= off) ? sl[e1 - off] : 0.f);
        float h0 = sh[e0] + ((e0 + off < 2048) ? sh[e0 + off] : 0.f);
        float h1 = sh[e1] + ((e1 + off < 2048) ? sh[e1 + off] : 0.f);
        __syncthreads();
        sl[e0] = l0; sl[e1] = l1;
        sh[e0] = h0; sh[e1] = h1;
        __syncthreads();
    }

    for (int e = tid; e < 2048; e += 1024) {
        g_sortedR[b * 2048 + e] = ss[e];
        g_cumLowEx[b * 2049 + e + 1] = sl[e];
        g_sufHigh[b * 2049 + e] = sh[e];
    }
    if (tid == 0) {
        g_cumLowEx[b * 2049] = 0.f;
        g_sufHigh[b * 2049 + 2048] = 0.f;
    }
}

// ---------------- kernel 5: A values at the K sparse slots (packed with idx) ----------------
__global__ void k_aval() {
    int g = blockIdx.x * blockDim.x + threadIdx.x;
    if (g >= NB * NN) return;
    int b = g / NN, i = g - b * NN;
    float l = g_left[g];
    float theta = -l;
    const float* sr = g_sortedR + b * 2048;
    int lo = 0, hi = 2048;
    while (lo < hi) {
        int mid = (lo + hi) >> 1;
        if (sr[mid] < theta) lo = mid + 1; else hi = mid;
    }
    int pos = lo;
    float denom = expf(l) * g_sufHigh[b * 2049 + pos]
                + expf(0.2f * l) * g_cumLowEx[b * 2049 + pos];
    float inv = 1.0f / denom;
    float2* pk = g_pk + (size_t)g * NK;
#pragma unroll
    for (int k = 0; k < NK; k++) {
        int j = g_idx[i * NK + k];
        float s = l + g_right[b * NN + j];
        float num = (s >= 0.f) ? expf(s) : expf(0.2f * s);
        float aval = num * inv + g_adj1v[i * NK + k];
        pk[k] = make_float2(aval, __int_as_float(j));
    }
}

// ---------------- kernel 6: fused 2-step propagation, smem float4 slabs, no shfl ----------------
// grid (NCHUNK, BT), 1024 threads, dynamic smem = 2 * NN float4 = 64 KB
__global__ void __launch_bounds__(1024, 2) k_prop(const float* __restrict__ x) {
    extern __shared__ float4 smem4[];
    float4* sx4 = smem4;          // x chunk, later h2 chunk (in-place)
    float4* sh4 = smem4 + NN;     // h1 chunk

    int tid = threadIdx.x;
    int chunk = blockIdx.x;
    int bt = blockIdx.y;
    int b = bt / NT, t = bt - b * NT;
    int ch0 = chunk * CH;

    // load x chunk slab (4 coalesced planes)
    const float* xs = x + ((size_t)(b * NC + ch0) * NT + t) * NN;
    for (int n = tid; n < NN; n += 1024) {
        float4 v;
        v.x = xs[n];
        v.y = xs[(size_t)NT * NN + n];
        v.z = xs[(size_t)2 * NT * NN + n];
        v.w = xs[(size_t)3 * NT * NN + n];
        sx4[n] = v;
    }
    __syncthreads();

    const float2* pkb = g_pk + (size_t)b * NN * NK;

    // ---- step 1: h1 = 0.05 x + 0.95 A x ----
    for (int m = tid; m < NN; m += 1024) {
        const float4* pk4 = reinterpret_cast<const float4*>(pkb + (size_t)m * NK);
        float4 acc = make_float4(0.f, 0.f, 0.f, 0.f);
#pragma unroll
        for (int q = 0; q < 10; q++) {
            float4 p = pk4[q];
            int j0 = __float_as_int(p.y);
            int j1 = __float_as_int(p.w);
            float4 v0 = sx4[j0];
            float4 v1 = sx4[j1];
            acc.x += p.x * v0.x + p.z * v1.x;
            acc.y += p.x * v0.y + p.z * v1.y;
            acc.z += p.x * v0.z + p.z * v1.z;
            acc.w += p.x * v0.w + p.z * v1.w;
        }
        float4 own = sx4[m];
        float4 h;
        h.x = 0.05f * own.x + 0.95f * acc.x;
        h.y = 0.05f * own.y + 0.95f * acc.y;
        h.z = 0.05f * own.z + 0.95f * acc.z;
        h.w = 0.05f * own.w + 0.95f * acc.w;
        sh4[m] = h;
    }
    __syncthreads();

    // ---- step 2: h2 = 0.05 x + 0.95 A h1 ; overwrite sx4 in place (own index only) ----
    for (int m = tid; m < NN; m += 1024) {
        const float4* pk4 = reinterpret_cast<const float4*>(pkb + (size_t)m * NK);
        float4 acc = make_float4(0.f, 0.f, 0.f, 0.f);
#pragma unroll
        for (int q = 0; q < 10; q++) {
            float4 p = pk4[q];
            int j0 = __float_as_int(p.y);
            int j1 = __float_as_int(p.w);
            float4 v0 = sh4[j0];
            float4 v1 = sh4[j1];
            acc.x += p.x * v0.x + p.z * v1.x;
            acc.y += p.x * v0.y + p.z * v1.y;
            acc.z += p.x * v0.z + p.z * v1.z;
            acc.w += p.x * v0.w + p.z * v1.w;
        }
        float4 own = sx4[m];
        float4 h;
        h.x = 0.05f * own.x + 0.95f * acc.x;
        h.y = 0.05f * own.y + 0.95f * acc.y;
        h.z = 0.05f * own.z + 0.95f * acc.z;
        h.w = 0.05f * own.w + 0.95f * acc.w;
        sx4[m] = h;
    }
    __syncthreads();

    // write h2 chunk (4 coalesced planes)
    float* h2 = g_h2 + ((size_t)bt * NC + ch0) * NN;
    for (int n = tid; n < NN; n += 1024) {
        float4 v = sx4[n];
        h2[n] = v.x;
        h2[(size_t)NN + n] = v.y;
        h2[(size_t)2 * NN + n] = v.z;
        h2[(size_t)3 * NN + n] = v.w;
    }
}

// ---------------- kernel 7: output projection ho = W1 h2 + b1 ----------------
__global__ void k_out(float* __restrict__ out, const float* __restrict__ W1,
                      const float* __restrict__ b1) {
    __shared__ float W1s[NC * NC];
    __shared__ float b1s[NC];
    int tid = threadIdx.x;
    for (int i = tid; i < NC * NC; i += 256) W1s[i] = W1[i];
    if (tid < NC) b1s[tid] = b1[tid];
    __syncthreads();
    int bt = blockIdx.y;
    int b = bt / NT, t = bt - b * NT;
    int n = blockIdx.x * 256 + tid;
    if (n >= NN) return;
    float h[NC];
#pragma unroll
    for (int cc = 0; cc < NC; cc++)
        h[cc] = g_h2[((size_t)bt * NC + cc) * NN + n];
#pragma unroll
    for (int o = 0; o < NC; o++) {
        float s = b1s[o];
#pragma unroll
        for (int cc = 0; cc < NC; cc++) s += W1s[o * NC + cc] * h[cc];
        out[((size_t)(b * NC + o) * NT + t) * NN + n] = s;
    }
}

// ---------------- launch ----------------
extern "C" void kernel_launch(void* const* d_in, const int* in_sizes, int n_in,
                              void* d_out, int out_size) {
    const float* x   = (const float*)d_in[0];
    const float* adj = (const float*)d_in[1];
    const float* W1  = (const float*)d_in[2];
    const float* b1  = (const float*)d_in[3];
    const float* W2  = (const float*)d_in[4];
    const float* b2  = (const float*)d_in[5];
    const float* a   = (const float*)d_in[6];
    float* out = (float*)d_out;

    int prop_smem = 2 * NN * (int)sizeof(float4);   // 64000 B
    cudaFuncSetAttribute(k_prop, cudaFuncAttributeMaxDynamicSharedMemorySize, prop_smem);

    k_adj<<<(NN + 3) / 4, 128>>>(adj);
    k_u<<<1, 512>>>(W2, b2, a);
    {
        dim3 grid(8, NB);
        k_lr<<<grid, 256>>>(x);
    }
    k_sort<<<NB, 1024>>>();
    k_aval<<<(NB * NN + 255) / 256, 256>>>();
    {
        dim3 grid(NCHUNK, BT);
        k_prop<<<grid, 1024, prop_smem>>>(x);
    }
    {
        dim3 grid(8, BT);
        k_out<<<grid, 256>>>(out, W1, b1);
    }
}

// round 7
// speedup vs baseline: 1.5578x; 1.4402x over previous
#include <cuda_runtime.h>
#include <math.h>

#define NB 16
#define NC 32
#define NT 13
#define NN 2000
#define NK 20
#define ND (NT*NC)      // 416
#define BT (NB*NT)      // 208
#define CH 8            // channels per prop chunk (two float4 slabs)
#define NCHUNK (NC/CH)  // 4

// ---------------- scratch (device globals; no allocation allowed) ----------------
__device__ float  g_h2[(size_t)BT*NC*NN];   // h after 2 prop steps, [bt][c][n]
__device__ float  g_left[NB*NN];
__device__ float  g_right[NB*NN];
__device__ int    g_idx[NN*NK];
__device__ float  g_adj1v[NN*NK];
__device__ float2 g_pk[(size_t)NB*NK*NN];   // TRANSPOSED: {Aval, idx bits} at [b][k][n]
__device__ float  g_sortedR[NB*2048];
__device__ float  g_sufHigh[NB*2049];
__device__ float  g_cumLowEx[NB*2049];
__device__ float  g_u1[ND];
__device__ float  g_u2[ND];
__device__ float  g_LR0[2];

// ---------------- kernel 1: adj relu + row-normalize + top-K (warp per row) ----------------
__global__ void k_adj(const float* __restrict__ adj) {
    __shared__ float sv[4 * NN];
    int warp = threadIdx.x >> 5, lane = threadIdx.x & 31;
    int row = blockIdx.x * 4 + warp;
    if (row >= NN) return;
    float* v = sv + warp * NN;
    const float* arow = adj + (size_t)row * NN;

    float psum = 0.f;
    float bv = -1.f; int bi = 0;
#pragma unroll 8
    for (int q = 0; q < 63; q++) {
        int e = lane + 32 * q;
        if (e < NN) {
            float xv = arow[e];
            xv = xv > 0.f ? xv : 0.f;
            v[e] = xv;
            psum += xv;
            if (xv > bv) { bv = xv; bi = e; }
        }
    }
#pragma unroll
    for (int o = 16; o > 0; o >>= 1) psum += __shfl_xor_sync(0xffffffffu, psum, o);
    float invdeg = 1.0f / psum;

    for (int it = 0; it < NK; it++) {
        float mv = bv; int mi = bi;
#pragma unroll
        for (int o = 16; o > 0; o >>= 1) {
            float ov = __shfl_xor_sync(0xffffffffu, mv, o);
            int   oi = __shfl_xor_sync(0xffffffffu, mi, o);
            if (ov > mv || (ov == mv && oi < mi)) { mv = ov; mi = oi; }
        }
        if (lane == 0) {
            g_idx[row * NK + it] = mi;
            g_adj1v[row * NK + it] = mv * invdeg;
        }
        if ((mi & 31) == lane) {   // winner lane removes + rescans its slice
            v[mi] = -2.0f;
            bv = -1.f; bi = 0;
#pragma unroll 8
            for (int q = 0; q < 63; q++) {
                int e = lane + 32 * q;
                if (e < NN) {
                    float xv = v[e];
                    if (xv > bv) { bv = xv; bi = e; }
                }
            }
        }
        __syncwarp();
    }
}

// ---------------- kernel 2: u1/u2 = a-slices folded into W2; bias constants ----------------
__global__ void k_u(const float* __restrict__ W2, const float* __restrict__ b2,
                    const float* __restrict__ a) {
    int tid = threadIdx.x;
    if (tid < ND) {
        int t = tid >> 5, c = tid & 31;
        float s1 = 0.f, s2 = 0.f;
        for (int o = 0; o < NC; o++) {
            float w = W2[o * NC + c];
            s1 += a[t * NC + o] * w;
            s2 += a[ND + t * NC + o] * w;
        }
        g_u1[tid] = s1;
        g_u2[tid] = s2;
    } else if (tid == ND) {
        float s = 0.f;
        for (int d = 0; d < ND; d++) s += b2[d & 31] * a[d];
        g_LR0[0] = s;
    } else if (tid == ND + 1) {
        float s = 0.f;
        for (int d = 0; d < ND; d++) s += b2[d & 31] * a[ND + d];
        g_LR0[1] = s;
    }
}

// ---------------- kernel 3: left/right directly from x (thread = node) ----------------
__global__ void k_lr(const float* __restrict__ x) {
    __shared__ float su1[ND], su2[ND];
    int tid = threadIdx.x;
    for (int i = tid; i < ND; i += 256) { su1[i] = g_u1[i]; su2[i] = g_u2[i]; }
    __syncthreads();
    int n = blockIdx.x * 256 + tid;
    int b = blockIdx.y;
    if (n >= NN) return;
    const float* xb = x + (size_t)b * NC * NT * NN + n;
    float s1 = 0.f, s2 = 0.f;
#pragma unroll 4
    for (int c = 0; c < NC; c++) {
#pragma unroll
        for (int t = 0; t < NT; t++) {
            float v = xb[(size_t)(c * NT + t) * NN];
            s1 += v * su1[t * NC + c];
            s2 += v * su2[t * NC + c];
        }
    }
    g_left[b * NN + n]  = s1 + g_LR0[0];
    g_right[b * NN + n] = s2 + g_LR0[1];
}

// ---------------- kernel 4: per-batch sort of right + prefix/suffix exp-sums ----------------
__global__ void k_sort() {
    __shared__ float ss[2048];
    __shared__ float sl[2048];
    __shared__ float sh[2048];
    int b = blockIdx.x;
    int tid = threadIdx.x;

    for (int e = tid; e < 2048; e += 1024)
        ss[e] = (e < NN) ? g_right[b * NN + e] : INFINITY;
    __syncthreads();

    for (int k2 = 2; k2 <= 2048; k2 <<= 1) {
        for (int j = k2 >> 1; j > 0; j >>= 1) {
            for (int e = tid; e < 2048; e += 1024) {
                int p = e ^ j;
                if (p > e) {
                    bool up = ((e & k2) == 0);
                    float av = ss[e], bvv = ss[p];
                    if ((av > bvv) == up) { ss[e] = bvv; ss[p] = av; }
                }
            }
            __syncthreads();
        }
    }

    for (int e = tid; e < 2048; e += 1024) {
        sl[e] = (e < NN) ? expf(0.2f * ss[e]) : 0.f;
        sh[e] = (e < NN) ? expf(ss[e]) : 0.f;
    }
    __syncthreads();

    for (int off = 1; off < 2048; off <<= 1) {
        int e0 = tid, e1 = tid + 1024;
        float l0 = sl[e0] + ((e0 >= off) ? sl[e0 - off] : 0.f);
        float l1 = sl[e1] + ((e1 >= off) ? sl[e1 - off] : 0.f);
        float h0 = sh[e0] + ((e0 + off < 2048) ? sh[e0 + off] : 0.f);
        float h1 = sh[e1] + ((e1 + off < 2048) ? sh[e1 + off] : 0.f);
        __syncthreads();
        sl[e0] = l0; sl[e1] = l1;
        sh[e0] = h0; sh[e1] = h1;
        __syncthreads();
    }

    for (int e = tid; e < 2048; e += 1024) {
        g_sortedR[b * 2048 + e] = ss[e];
        g_cumLowEx[b * 2049 + e + 1] = sl[e];
        g_sufHigh[b * 2049 + e] = sh[e];
    }
    if (tid == 0) {
        g_cumLowEx[b * 2049] = 0.f;
        g_sufHigh[b * 2049 + 2048] = 0.f;
    }
}

// ---------------- kernel 5: A values, written TRANSPOSED to [b][k][n] ----------------
__global__ void k_aval() {
    int g = blockIdx.x * blockDim.x + threadIdx.x;
    if (g >= NB * NN) return;
    int b = g / NN, i = g - b * NN;
    float l = g_left[g];
    float theta = -l;
    const float* sr = g_sortedR + b * 2048;
    int lo = 0, hi = 2048;
    while (lo < hi) {
        int mid = (lo + hi) >> 1;
        if (sr[mid] < theta) lo = mid + 1; else hi = mid;
    }
    int pos = lo;
    float denom = expf(l) * g_sufHigh[b * 2049 + pos]
                + expf(0.2f * l) * g_cumLowEx[b * 2049 + pos];
    float inv = 1.0f / denom;
    float2* pkb = g_pk + (size_t)b * NK * NN;
#pragma unroll
    for (int k = 0; k < NK; k++) {
        int j = g_idx[i * NK + k];
        float s = l + g_right[b * NN + j];
        float num = (s >= 0.f) ? expf(s) : expf(0.2f * s);
        float aval = num * inv + g_adj1v[i * NK + k];
        pkb[(size_t)k * NN + i] = make_float2(aval, __int_as_float(j));
    }
}

// ---------------- kernel 6: fused 2-step propagation, CH=8, coalesced pk ----------------
// grid (NCHUNK, BT), 1024 threads, dynamic smem = 4 * NN float4 = 128 KB
__global__ void __launch_bounds__(1024, 1) k_prop(const float* __restrict__ x) {
    extern __shared__ float4 smem4[];
    float4* sxA = smem4;              // x ch 0-3  (later h2 ch 0-3, in place)
    float4* sxB = smem4 + NN;         // x ch 4-7
    float4* shA = smem4 + 2 * NN;     // h1 ch 0-3
    float4* shB = smem4 + 3 * NN;     // h1 ch 4-7

    int tid = threadIdx.x;
    int chunk = blockIdx.x;
    int bt = blockIdx.y;
    int b = bt / NT, t = bt - b * NT;
    int ch0 = chunk * CH;

    const size_t P = (size_t)NT * NN;   // plane stride in x
    const float* xs = x + ((size_t)(b * NC + ch0) * NT + t) * NN;
    for (int n = tid; n < NN; n += 1024) {
        float4 va, vb;
        va.x = xs[n];         va.y = xs[P + n];     va.z = xs[2*P + n];  va.w = xs[3*P + n];
        vb.x = xs[4*P + n];   vb.y = xs[5*P + n];   vb.z = xs[6*P + n];  vb.w = xs[7*P + n];
        sxA[n] = va;
        sxB[n] = vb;
    }
    __syncthreads();

    const float2* pkb = g_pk + (size_t)b * NK * NN;

    // ---- step 1: h1 = 0.05 x + 0.95 A x ----
    for (int m = tid; m < NN; m += 1024) {
        float4 accA = make_float4(0.f, 0.f, 0.f, 0.f);
        float4 accB = make_float4(0.f, 0.f, 0.f, 0.f);
#pragma unroll
        for (int k = 0; k < NK; k++) {
            float2 p = pkb[(size_t)k * NN + m];       // coalesced LDG.64
            int j = __float_as_int(p.y);
            float4 vA = sxA[j];
            float4 vB = sxB[j];
            accA.x += p.x * vA.x; accA.y += p.x * vA.y;
            accA.z += p.x * vA.z; accA.w += p.x * vA.w;
            accB.x += p.x * vB.x; accB.y += p.x * vB.y;
            accB.z += p.x * vB.z; accB.w += p.x * vB.w;
        }
        float4 oA = sxA[m], oB = sxB[m];
        float4 hA, hB;
        hA.x = 0.05f*oA.x + 0.95f*accA.x;  hA.y = 0.05f*oA.y + 0.95f*accA.y;
        hA.z = 0.05f*oA.z + 0.95f*accA.z;  hA.w = 0.05f*oA.w + 0.95f*accA.w;
        hB.x = 0.05f*oB.x + 0.95f*accB.x;  hB.y = 0.05f*oB.y + 0.95f*accB.y;
        hB.z = 0.05f*oB.z + 0.95f*accB.z;  hB.w = 0.05f*oB.w + 0.95f*accB.w;
        shA[m] = hA;
        shB[m] = hB;
    }
    __syncthreads();

    // ---- step 2: h2 = 0.05 x + 0.95 A h1 ; overwrite sx in place (own index only) ----
    for (int m = tid; m < NN; m += 1024) {
        float4 accA = make_float4(0.f, 0.f, 0.f, 0.f);
        float4 accB = make_float4(0.f, 0.f, 0.f, 0.f);
#pragma unroll
        for (int k = 0; k < NK; k++) {
            float2 p = pkb[(size_t)k * NN + m];
            int j = __float_as_int(p.y);
            float4 vA = shA[j];
            float4 vB = shB[j];
            accA.x += p.x * vA.x; accA.y += p.x * vA.y;
            accA.z += p.x * vA.z; accA.w += p.x * vA.w;
            accB.x += p.x * vB.x; accB.y += p.x * vB.y;
            accB.z += p.x * vB.z; accB.w += p.x * vB.w;
        }
        float4 oA = sxA[m], oB = sxB[m];
        float4 hA, hB;
        hA.x = 0.05f*oA.x + 0.95f*accA.x;  hA.y = 0.05f*oA.y + 0.95f*accA.y;
        hA.z = 0.05f*oA.z + 0.95f*accA.z;  hA.w = 0.05f*oA.w + 0.95f*accA.w;
        hB.x = 0.05f*oB.x + 0.95f*accB.x;  hB.y = 0.05f*oB.y + 0.95f*accB.y;
        hB.z = 0.05f*oB.z + 0.95f*accB.z;  hB.w = 0.05f*oB.w + 0.95f*accB.w;
        sxA[m] = hA;
        sxB[m] = hB;
    }
    __syncthreads();

    // write h2 chunk (8 coalesced planes)
    float* h2 = g_h2 + ((size_t)bt * NC + ch0) * NN;
    for (int n = tid; n < NN; n += 1024) {
        float4 va = sxA[n], vb = sxB[n];
        h2[n]              = va.x;
        h2[(size_t)NN + n]   = va.y;
        h2[(size_t)2*NN + n] = va.z;
        h2[(size_t)3*NN + n] = va.w;
        h2[(size_t)4*NN + n] = vb.x;
        h2[(size_t)5*NN + n] = vb.y;
        h2[(size_t)6*NN + n] = vb.z;
        h2[(size_t)7*NN + n] = vb.w;
    }
}

// ---------------- kernel 7: output projection ho = W1 h2 + b1 ----------------
__global__ void k_out(float* __restrict__ out, const float* __restrict__ W1,
                      const float* __restrict__ b1) {
    __shared__ float W1s[NC * NC];
    __shared__ float b1s[NC];
    int tid = threadIdx.x;
    for (int i = tid; i < NC * NC; i += 256) W1s[i] = W1[i];
    if (tid < NC) b1s[tid] = b1[tid];
    __syncthreads();
    int bt = blockIdx.y;
    int b = bt / NT, t = bt - b * NT;
    int n = blockIdx.x * 256 + tid;
    if (n >= NN) return;
    float h[NC];
#pragma unroll
    for (int cc = 0; cc < NC; cc++)
        h[cc] = g_h2[((size_t)bt * NC + cc) * NN + n];
#pragma unroll
    for (int o = 0; o < NC; o++) {
        float s = b1s[o];
#pragma unroll
        for (int cc = 0; cc < NC; cc++) s += W1s[o * NC + cc] * h[cc];
        out[((size_t)(b * NC + o) * NT + t) * NN + n] = s;
    }
}

// ---------------- launch ----------------
extern "C" void kernel_launch(void* const* d_in, const int* in_sizes, int n_in,
                              void* d_out, int out_size) {
    const float* x   = (const float*)d_in[0];
    const float* adj = (const float*)d_in[1];
    const float* W1  = (const float*)d_in[2];
    const float* b1  = (const float*)d_in[3];
    const float* W2  = (const float*)d_in[4];
    const float* b2  = (const float*)d_in[5];
    const float* a   = (const float*)d_in[6];
    float* out = (float*)d_out;

    int prop_smem = 4 * NN * (int)sizeof(float4);   // 128000 B
    cudaFuncSetAttribute(k_prop, cudaFuncAttributeMaxDynamicSharedMemorySize, prop_smem);

    k_adj<<<(NN + 3) / 4, 128>>>(adj);
    k_u<<<1, 512>>>(W2, b2, a);
    {
        dim3 grid(8, NB);
        k_lr<<<grid, 256>>>(x);
    }
    k_sort<<<NB, 1024>>>();
    k_aval<<<(NB * NN + 255) / 256, 256>>>();
    {
        dim3 grid(NCHUNK, BT);
        k_prop<<<grid, 1024, prop_smem>>>(x);
    }
    {
        dim3 grid(8, BT);
        k_out<<<grid, 256>>>(out, W1, b1);
    }
}

// round 8
// speedup vs baseline: 2.2393x; 1.4374x over previous
#include <cuda_runtime.h>
#include <cuda_fp16.h>
#include <math.h>

#define NB 16
#define NC 32
#define NT 13
#define NN 2000
#define NK 20
#define ND (NT*NC)      // 416
#define BT (NB*NT)      // 208
#define CH 8            // channels per prop chunk (packed as 4 half2 = 16B)
#define NCHUNK (NC/CH)  // 4
#define PB 512          // k_prop block size

#define ADJ_BLOCKS 500  // 4 rows per block
#define LR_BLOCKS  250  // 32000 / 128

// ---------------- scratch (device globals; no allocation allowed) ----------------
__device__ float  g_h2[(size_t)BT*NC*NN];   // h after 2 prop steps, [bt][c][n]
__device__ float  g_left[NB*NN];
__device__ float  g_right[NB*NN];
__device__ int    g_idx[NN*NK];
__device__ float  g_adj1v[NN*NK];
__device__ float2 g_pk[(size_t)NB*NK*NN];   // {Aval, idx bits} at [b][k][n] (coalesced)
__device__ float  g_sortedR[NB*2048];
__device__ float  g_sufHigh[NB*2049];
__device__ float  g_cumLowEx[NB*2049];
__device__ float  g_u1[ND];
__device__ float  g_u2[ND];
__device__ float  g_LR0[2];

// ---------------- kernel 1: u1/u2 = a-slices folded into W2; bias constants ----------------
__global__ void k_u(const float* __restrict__ W2, const float* __restrict__ b2,
                    const float* __restrict__ a) {
    int tid = threadIdx.x;
    if (tid < ND) {
        int t = tid >> 5, c = tid & 31;
        float s1 = 0.f, s2 = 0.f;
        for (int o = 0; o < NC; o++) {
            float w = W2[o * NC + c];
            s1 += a[t * NC + o] * w;
            s2 += a[ND + t * NC + o] * w;
        }
        g_u1[tid] = s1;
        g_u2[tid] = s2;
    } else if (tid == ND) {
        float s = 0.f;
        for (int d = 0; d < ND; d++) s += b2[d & 31] * a[d];
        g_LR0[0] = s;
    } else if (tid == ND + 1) {
        float s = 0.f;
        for (int d = 0; d < ND; d++) s += b2[d & 31] * a[ND + d];
        g_LR0[1] = s;
    }
}

// ---------------- kernel 2: FUSED  [adj relu+norm+topK]  ||  [left/right] ----------------
// blocks [0, ADJ_BLOCKS): top-K, 4 rows per block (warp per row), smem = 4*NN floats
// blocks [ADJ_BLOCKS, +LR_BLOCKS): left/right, 128 (b,n) pairs per block
__global__ void k_adjlr(const float* __restrict__ adj, const float* __restrict__ x) {
    extern __shared__ float dsm[];
    if (blockIdx.x < ADJ_BLOCKS) {
        int warp = threadIdx.x >> 5, lane = threadIdx.x & 31;
        int row = blockIdx.x * 4 + warp;
        if (row >= NN) return;
        float* v = dsm + warp * NN;
        const float* arow = adj + (size_t)row * NN;

        float psum = 0.f;
        float bv = -1.f; int bi = 0;
#pragma unroll 8
        for (int q = 0; q < 63; q++) {
            int e = lane + 32 * q;
            if (e < NN) {
                float xv = arow[e];
                xv = xv > 0.f ? xv : 0.f;
                v[e] = xv;
                psum += xv;
                if (xv > bv) { bv = xv; bi = e; }
            }
        }
#pragma unroll
        for (int o = 16; o > 0; o >>= 1) psum += __shfl_xor_sync(0xffffffffu, psum, o);
        float invdeg = 1.0f / psum;

        for (int it = 0; it < NK; it++) {
            float mv = bv; int mi = bi;
#pragma unroll
            for (int o = 16; o > 0; o >>= 1) {
                float ov = __shfl_xor_sync(0xffffffffu, mv, o);
                int   oi = __shfl_xor_sync(0xffffffffu, mi, o);
                if (ov > mv || (ov == mv && oi < mi)) { mv = ov; mi = oi; }
            }
            if (lane == 0) {
                g_idx[row * NK + it] = mi;
                g_adj1v[row * NK + it] = mv * invdeg;
            }
            if ((mi & 31) == lane) {   // winner lane removes + rescans its slice
                v[mi] = -2.0f;
                bv = -1.f; bi = 0;
#pragma unroll 8
                for (int q = 0; q < 63; q++) {
                    int e = lane + 32 * q;
                    if (e < NN) {
                        float xv = v[e];
                        if (xv > bv) { bv = xv; bi = e; }
                    }
                }
            }
            __syncwarp();
        }
    } else {
        float* su1 = dsm;
        float* su2 = dsm + ND;
        int tid = threadIdx.x;
        for (int i = tid; i < ND; i += 128) { su1[i] = g_u1[i]; su2[i] = g_u2[i]; }
        __syncthreads();
        int g = (blockIdx.x - ADJ_BLOCKS) * 128 + tid;   // 0..31999
        int b = g / NN, n = g - b * NN;
        const float* xb = x + (size_t)b * NC * NT * NN + n;
        float s1 = 0.f, s2 = 0.f;
#pragma unroll 4
        for (int c = 0; c < NC; c++) {
#pragma unroll
            for (int t = 0; t < NT; t++) {
                float v = xb[(size_t)(c * NT + t) * NN];
                s1 += v * su1[t * NC + c];
                s2 += v * su2[t * NC + c];
            }
        }
        g_left[g]  = s1 + g_LR0[0];
        g_right[g] = s2 + g_LR0[1];
    }
}

// ---------------- kernel 3: per-batch sort of right + prefix/suffix exp-sums ----------------
__global__ void k_sort() {
    __shared__ float ss[2048];
    __shared__ float sl[2048];
    __shared__ float sh[2048];
    int b = blockIdx.x;
    int tid = threadIdx.x;

    for (int e = tid; e < 2048; e += 1024)
        ss[e] = (e < NN) ? g_right[b * NN + e] : INFINITY;
    __syncthreads();

    for (int k2 = 2; k2 <= 2048; k2 <<= 1) {
        for (int j = k2 >> 1; j > 0; j >>= 1) {
            for (int e = tid; e < 2048; e += 1024) {
                int p = e ^ j;
                if (p > e) {
                    bool up = ((e & k2) == 0);
                    float av = ss[e], bvv = ss[p];
                    if ((av > bvv) == up) { ss[e] = bvv; ss[p] = av; }
                }
            }
            __syncthreads();
        }
    }

    for (int e = tid; e < 2048; e += 1024) {
        sl[e] = (e < NN) ? expf(0.2f * ss[e]) : 0.f;
        sh[e] = (e < NN) ? expf(ss[e]) : 0.f;
    }
    __syncthreads();

    for (int off = 1; off < 2048; off <<= 1) {
        int e0 = tid, e1 = tid + 1024;
        float l0 = sl[e0] + ((e0 >= off) ? sl[e0 - off] : 0.f);
        float l1 = sl[e1] + ((e1 >= off) ? sl[e1 - off] : 0.f);
        float h0 = sh[e0] + ((e0 + off < 2048) ? sh[e0 + off] : 0.f);
        float h1 = sh[e1] + ((e1 + off < 2048) ? sh[e1 + off] : 0.f);
        __syncthreads();
        sl[e0] = l0; sl[e1] = l1;
        sh[e0] = h0; sh[e1] = h1;
        __syncthreads();
    }

    for (int e = tid; e < 2048; e += 1024) {
        g_sortedR[b * 2048 + e] = ss[e];
        g_cumLowEx[b * 2049 + e + 1] = sl[e];
        g_sufHigh[b * 2049 + e] = sh[e];
    }
    if (tid == 0) {
        g_cumLowEx[b * 2049] = 0.f;
        g_sufHigh[b * 2049 + 2048] = 0.f;
    }
}

// ---------------- kernel 4: A values, written to [b][k][n] ----------------
__global__ void k_aval() {
    int g = blockIdx.x * blockDim.x + threadIdx.x;
    if (g >= NB * NN) return;
    int b = g / NN, i = g - b * NN;
    float l = g_left[g];
    float theta = -l;
    const float* sr = g_sortedR + b * 2048;
    int lo = 0, hi = 2048;
    while (lo < hi) {
        int mid = (lo + hi) >> 1;
        if (sr[mid] < theta) lo = mid + 1; else hi = mid;
    }
    int pos = lo;
    float denom = expf(l) * g_sufHigh[b * 2049 + pos]
                + expf(0.2f * l) * g_cumLowEx[b * 2049 + pos];
    float inv = 1.0f / denom;
    float2* pkb = g_pk + (size_t)b * NK * NN;
#pragma unroll
    for (int k = 0; k < NK; k++) {
        int j = g_idx[i * NK + k];
        float s = l + g_right[b * NN + j];
        float num = (s >= 0.f) ? expf(s) : expf(0.2f * s);
        float aval = num * inv + g_adj1v[i * NK + k];
        pkb[(size_t)k * NN + i] = make_float2(aval, __int_as_float(j));
    }
}

// ---------------- kernel 5: fused 2-step propagation, fp16 slabs, fp32 math ----------------
// grid (NCHUNK, BT), PB=512 threads, dynamic smem = 2 * NN * 16B = 64 KB, occ 2
__device__ __forceinline__ void unpack8(uint4 u, float2& f0, float2& f1, float2& f2, float2& f3) {
    f0 = __half22float2(*reinterpret_cast<__half2*>(&u.x));
    f1 = __half22float2(*reinterpret_cast<__half2*>(&u.y));
    f2 = __half22float2(*reinterpret_cast<__half2*>(&u.z));
    f3 = __half22float2(*reinterpret_cast<__half2*>(&u.w));
}

__global__ void __launch_bounds__(PB, 2) k_prop(const float* __restrict__ x) {
    extern __shared__ uint4 smv[];
    uint4* sx = smv;          // x chunk, fp16x8 per node
    uint4* sh = smv + NN;     // h1 chunk

    int tid = threadIdx.x;
    int chunk = blockIdx.x;
    int bt = blockIdx.y;
    int b = bt / NT, t = bt - b * NT;
    int ch0 = chunk * CH;

    const size_t P = (size_t)NT * NN;
    const float* xs = x + ((size_t)(b * NC + ch0) * NT + t) * NN;
    for (int n = tid; n < NN; n += PB) {
        uint4 u;
        *reinterpret_cast<__half2*>(&u.x) = __float22half2_rn(make_float2(xs[n],       xs[P + n]));
        *reinterpret_cast<__half2*>(&u.y) = __float22half2_rn(make_float2(xs[2*P + n], xs[3*P + n]));
        *reinterpret_cast<__half2*>(&u.z) = __float22half2_rn(make_float2(xs[4*P + n], xs[5*P + n]));
        *reinterpret_cast<__half2*>(&u.w) = __float22half2_rn(make_float2(xs[6*P + n], xs[7*P + n]));
        sx[n] = u;
    }
    __syncthreads();

    const float2* pkb = g_pk + (size_t)b * NK * NN;

    // ---- step 1: h1 = 0.05 x + 0.95 A x  (gathers from sx, result packed to sh) ----
    for (int m = tid; m < NN; m += PB) {
        float2 a0 = {0.f,0.f}, a1 = {0.f,0.f}, a2 = {0.f,0.f}, a3 = {0.f,0.f};
#pragma unroll
        for (int k = 0; k < NK; k++) {
            float2 p = pkb[(size_t)k * NN + m];       // coalesced LDG.64
            int j = __float_as_int(p.y);
            float2 f0, f1, f2, f3; unpack8(sx[j], f0, f1, f2, f3);
            a0.x += p.x*f0.x; a0.y += p.x*f0.y;
            a1.x += p.x*f1.x; a1.y += p.x*f1.y;
            a2.x += p.x*f2.x; a2.y += p.x*f2.y;
            a3.x += p.x*f3.x; a3.y += p.x*f3.y;
        }
        float2 o0, o1, o2, o3; unpack8(sx[m], o0, o1, o2, o3);
        uint4 u;
        *reinterpret_cast<__half2*>(&u.x) = __float22half2_rn(
            make_float2(0.05f*o0.x + 0.95f*a0.x, 0.05f*o0.y + 0.95f*a0.y));
        *reinterpret_cast<__half2*>(&u.y) = __float22half2_rn(
            make_float2(0.05f*o1.x + 0.95f*a1.x, 0.05f*o1.y + 0.95f*a1.y));
        *reinterpret_cast<__half2*>(&u.z) = __float22half2_rn(
            make_float2(0.05f*o2.x + 0.95f*a2.x, 0.05f*o2.y + 0.95f*a2.y));
        *reinterpret_cast<__half2*>(&u.w) = __float22half2_rn(
            make_float2(0.05f*o3.x + 0.95f*a3.x, 0.05f*o3.y + 0.95f*a3.y));
        sh[m] = u;
    }
    __syncthreads();

    // ---- step 2: h2 = 0.05 x + 0.95 A h1 ; write fp32 result straight to GMEM ----
    float* h2 = g_h2 + ((size_t)bt * NC + ch0) * NN;
    for (int m = tid; m < NN; m += PB) {
        float2 a0 = {0.f,0.f}, a1 = {0.f,0.f}, a2 = {0.f,0.f}, a3 = {0.f,0.f};
#pragma unroll
        for (int k = 0; k < NK; k++) {
            float2 p = pkb[(size_t)k * NN + m];
            int j = __float_as_int(p.y);
            float2 f0, f1, f2, f3; unpack8(sh[j], f0, f1, f2, f3);
            a0.x += p.x*f0.x; a0.y += p.x*f0.y;
            a1.x += p.x*f1.x; a1.y += p.x*f1.y;
            a2.x += p.x*f2.x; a2.y += p.x*f2.y;
            a3.x += p.x*f3.x; a3.y += p.x*f3.y;
        }
        float2 o0, o1, o2, o3; unpack8(sx[m], o0, o1, o2, o3);
        h2[m]              = 0.05f*o0.x + 0.95f*a0.x;
        h2[(size_t)NN + m]   = 0.05f*o0.y + 0.95f*a0.y;
        h2[(size_t)2*NN + m] = 0.05f*o1.x + 0.95f*a1.x;
        h2[(size_t)3*NN + m] = 0.05f*o1.y + 0.95f*a1.y;
        h2[(size_t)4*NN + m] = 0.05f*o2.x + 0.95f*a2.x;
        h2[(size_t)5*NN + m] = 0.05f*o2.y + 0.95f*a2.y;
        h2[(size_t)6*NN + m] = 0.05f*o3.x + 0.95f*a3.x;
        h2[(size_t)7*NN + m] = 0.05f*o3.y + 0.95f*a3.y;
    }
}

// ---------------- kernel 6: output projection ho = W1 h2 + b1 ----------------
__global__ void k_out(float* __restrict__ out, const float* __restrict__ W1,
                      const float* __restrict__ b1) {
    __shared__ float W1s[NC * NC];
    __shared__ float b1s[NC];
    int tid = threadIdx.x;
    for (int i = tid; i < NC * NC; i += 256) W1s[i] = W1[i];
    if (tid < NC) b1s[tid] = b1[tid];
    __syncthreads();
    int bt = blockIdx.y;
    int b = bt / NT, t = bt - b * NT;
    int n = blockIdx.x * 256 + tid;
    if (n >= NN) return;
    float h[NC];
#pragma unroll
    for (int cc = 0; cc < NC; cc++)
        h[cc] = g_h2[((size_t)bt * NC + cc) * NN + n];
#pragma unroll
    for (int o = 0; o < NC; o++) {
        float s = b1s[o];
#pragma unroll
        for (int cc = 0; cc < NC; cc++) s += W1s[o * NC + cc] * h[cc];
        out[((size_t)(b * NC + o) * NT + t) * NN + n] = s;
    }
}

// ---------------- launch ----------------
extern "C" void kernel_launch(void* const* d_in, const int* in_sizes, int n_in,
                              void* d_out, int out_size) {
    const float* x   = (const float*)d_in[0];
    const float* adj = (const float*)d_in[1];
    const float* W1  = (const float*)d_in[2];
    const float* b1  = (const float*)d_in[3];
    const float* W2  = (const float*)d_in[4];
    const float* b2  = (const float*)d_in[5];
    const float* a   = (const float*)d_in[6];
    float* out = (float*)d_out;

    int prop_smem = 2 * NN * (int)sizeof(uint4);    // 64000 B
    cudaFuncSetAttribute(k_prop, cudaFuncAttributeMaxDynamicSharedMemorySize, prop_smem);
    int adjlr_smem = 4 * NN * (int)sizeof(float);   // 32000 B
    cudaFuncSetAttribute(k_adjlr, cudaFuncAttributeMaxDynamicSharedMemorySize, adjlr_smem);

    k_u<<<1, 512>>>(W2, b2, a);
    k_adjlr<<<ADJ_BLOCKS + LR_BLOCKS, 128, adjlr_smem>>>(adj, x);
    k_sort<<<NB, 1024>>>();
    k_aval<<<(NB * NN + 255) / 256, 256>>>();
    {
        dim3 grid(NCHUNK, BT);
        k_prop<<<grid, PB, prop_smem>>>(x);
    }
    {
        dim3 grid(8, BT);
        k_out<<<grid, 256>>>(out, W1, b1);
    }
}

// round 9
// speedup vs baseline: 2.4123x; 1.0773x over previous
#include <cuda_runtime.h>
#include <cuda_fp16.h>
#include <math.h>

#define NB 16
#define NC 32
#define NT 13
#define NN 2000
#define NK 20
#define ND (NT*NC)      // 416
#define BT (NB*NT)      // 208
#define CH 8            // channels per prop chunk (packed as 4 half2 = 16B)
#define NCHUNK (NC/CH)  // 4
#define PB 512          // k_prop block size

#define ADJ_BLOCKS 500  // 4 rows per block
#define LR_BLOCKS  250  // 32000 / 128

// ---------------- scratch (device globals; no allocation allowed) ----------------
__device__ float    g_h2[(size_t)BT*NC*NN];  // h after 2 prop steps, [bt][c][n]
__device__ float    g_left[NB*NN];
__device__ float    g_right[NB*NN];
__device__ int      g_idx_t[NK*NN];          // TRANSPOSED [k][n]
__device__ float    g_adj1v_t[NK*NN];        // TRANSPOSED [k][n]
__device__ unsigned g_pku[(size_t)NB*NK*NN]; // packed {half aval | uint16 idx} at [b][k][n]
__device__ float    g_sortedR[NB*2048];
__device__ float    g_sufHigh[NB*2049];
__device__ float    g_cumLowEx[NB*2049];
__device__ float    g_u1[ND];
__device__ float    g_u2[ND];
__device__ float    g_LR0[2];

// ---------------- kernel 1: u1/u2 = a-slices folded into W2; bias constants ----------------
__global__ void k_u(const float* __restrict__ W2, const float* __restrict__ b2,
                    const float* __restrict__ a) {
    int tid = threadIdx.x;
    if (tid < ND) {
        int t = tid >> 5, c = tid & 31;
        float s1 = 0.f, s2 = 0.f;
        for (int o = 0; o < NC; o++) {
            float w = W2[o * NC + c];
            s1 += a[t * NC + o] * w;
            s2 += a[ND + t * NC + o] * w;
        }
        g_u1[tid] = s1;
        g_u2[tid] = s2;
    } else if (tid == ND) {
        float s = 0.f;
        for (int d = 0; d < ND; d++) s += b2[d & 31] * a[d];
        g_LR0[0] = s;
    } else if (tid == ND + 1) {
        float s = 0.f;
        for (int d = 0; d < ND; d++) s += b2[d & 31] * a[ND + d];
        g_LR0[1] = s;
    }
}

// ---------------- kernel 2: FUSED  [adj relu+norm+topK]  ||  [left/right] ----------------
__global__ void k_adjlr(const float* __restrict__ adj, const float* __restrict__ x) {
    extern __shared__ float dsm[];
    if (blockIdx.x < ADJ_BLOCKS) {
        int warp = threadIdx.x >> 5, lane = threadIdx.x & 31;
        int row = blockIdx.x * 4 + warp;
        if (row >= NN) return;
        float* v = dsm + warp * NN;
        const float* arow = adj + (size_t)row * NN;

        float psum = 0.f;
        float bv = -1.f; int bi = 0;
#pragma unroll 8
        for (int q = 0; q < 63; q++) {
            int e = lane + 32 * q;
            if (e < NN) {
                float xv = arow[e];
                xv = xv > 0.f ? xv : 0.f;
                v[e] = xv;
                psum += xv;
                if (xv > bv) { bv = xv; bi = e; }
            }
        }
#pragma unroll
        for (int o = 16; o > 0; o >>= 1) psum += __shfl_xor_sync(0xffffffffu, psum, o);
        float invdeg = 1.0f / psum;

        for (int it = 0; it < NK; it++) {
            float mv = bv; int mi = bi;
#pragma unroll
            for (int o = 16; o > 0; o >>= 1) {
                float ov = __shfl_xor_sync(0xffffffffu, mv, o);
                int   oi = __shfl_xor_sync(0xffffffffu, mi, o);
                if (ov > mv || (ov == mv && oi < mi)) { mv = ov; mi = oi; }
            }
            if (lane == 0) {
                g_idx_t[it * NN + row]   = mi;          // transposed write
                g_adj1v_t[it * NN + row] = mv * invdeg;
            }
            if ((mi & 31) == lane) {   // winner lane removes + rescans its slice
                v[mi] = -2.0f;
                bv = -1.f; bi = 0;
#pragma unroll 8
                for (int q = 0; q < 63; q++) {
                    int e = lane + 32 * q;
                    if (e < NN) {
                        float xv = v[e];
                        if (xv > bv) { bv = xv; bi = e; }
                    }
                }
            }
            __syncwarp();
        }
    } else {
        float* su1 = dsm;
        float* su2 = dsm + ND;
        int tid = threadIdx.x;
        for (int i = tid; i < ND; i += 128) { su1[i] = g_u1[i]; su2[i] = g_u2[i]; }
        __syncthreads();
        int g = (blockIdx.x - ADJ_BLOCKS) * 128 + tid;   // 0..31999
        int b = g / NN, n = g - b * NN;
        const float* xb = x + (size_t)b * NC * NT * NN + n;
        float s1 = 0.f, s2 = 0.f;
#pragma unroll 4
        for (int c = 0; c < NC; c++) {
#pragma unroll
            for (int t = 0; t < NT; t++) {
                float v = xb[(size_t)(c * NT + t) * NN];
                s1 += v * su1[t * NC + c];
                s2 += v * su2[t * NC + c];
            }
        }
        g_left[g]  = s1 + g_LR0[0];
        g_right[g] = s2 + g_LR0[1];
    }
}

// ---------------- kernel 3: sort (warp-shfl bitonic) + shfl scans ----------------
__global__ void k_sort() {
    __shared__ float ss[2048];
    __shared__ float wsum[32];
    int b = blockIdx.x;
    int tid = threadIdx.x;
    int lane = tid & 31, warp = tid >> 5;

    ss[tid]        = (tid < NN)        ? g_right[b * NN + tid]        : INFINITY;
    ss[tid + 1024] = (tid + 1024 < NN) ? g_right[b * NN + tid + 1024] : INFINITY;
    __syncthreads();

    // bitonic ascending; j<32 stages via shfl (element e=tid lives on lane e&31)
    for (int k2 = 2; k2 <= 2048; k2 <<= 1) {
        for (int j = k2 >> 1; j >= 32; j >>= 1) {
#pragma unroll
            for (int r = 0; r < 2; r++) {
                int e = tid + r * 1024;
                int p = e ^ j;
                if (p > e) {
                    bool up = ((e & k2) == 0);
                    float av = ss[e], bvv = ss[p];
                    if ((av > bvv) == up) { ss[e] = bvv; ss[p] = av; }
                }
            }
            __syncthreads();
        }
        int e0 = tid, e1 = tid + 1024;
        float r0 = ss[e0], r1 = ss[e1];
        bool up0 = ((e0 & k2) == 0);
        bool up1 = ((e1 & k2) == 0);
        int jstart = (k2 >= 32) ? 16 : (k2 >> 1);
        for (int j = jstart; j >= 1; j >>= 1) {
            float p0 = __shfl_xor_sync(0xffffffffu, r0, j);
            float p1 = __shfl_xor_sync(0xffffffffu, r1, j);
            bool lo0 = ((e0 & j) == 0);
            bool lo1 = ((e1 & j) == 0);
            r0 = (lo0 == up0) ? fminf(r0, p0) : fmaxf(r0, p0);
            r1 = (lo1 == up1) ? fminf(r1, p1) : fmaxf(r1, p1);
        }
        ss[e0] = r0; ss[e1] = r1;
        __syncthreads();
    }

    g_sortedR[b * 2048 + tid]        = ss[tid];
    g_sortedR[b * 2048 + tid + 1024] = ss[tid + 1024];

    // ---- prefix scan of exp(0.2*sorted) (ascending): thread owns pair (2t, 2t+1) ----
    {
        int e0 = 2 * tid, e1 = 2 * tid + 1;
        float v0 = (e0 < NN) ? expf(0.2f * ss[e0]) : 0.f;
        float v1 = (e1 < NN) ? expf(0.2f * ss[e1]) : 0.f;
        float s = v0 + v1;
        float sc = s;
#pragma unroll
        for (int o = 1; o < 32; o <<= 1) {
            float nn = __shfl_up_sync(0xffffffffu, sc, o);
            if (lane >= o) sc += nn;
        }
        if (lane == 31) wsum[warp] = sc;
        __syncthreads();
        if (tid < 32) {
            float v = wsum[tid];
            float scv = v;
#pragma unroll
            for (int o = 1; o < 32; o <<= 1) {
                float nn = __shfl_up_sync(0xffffffffu, scv, o);
                if (tid >= o) scv += nn;
            }
            wsum[tid] = scv - v;   // exclusive warp offset
        }
        __syncthreads();
        float base = wsum[warp] + (sc - s);
        g_cumLowEx[b * 2049 + e0 + 1] = base + v0;
        g_cumLowEx[b * 2049 + e1 + 1] = base + v0 + v1;
        if (tid == 0) g_cumLowEx[b * 2049] = 0.f;
        __syncthreads();
    }

    // ---- suffix scan of exp(sorted): reversed prefix; thread owns rev-pos (2t, 2t+1) ----
    {
        int e0 = 2047 - 2 * tid;      // rev-pos 2t
        int e1 = 2046 - 2 * tid;      // rev-pos 2t+1
        float v0 = (e0 < NN) ? expf(ss[e0]) : 0.f;
        float v1 = (e1 < NN) ? expf(ss[e1]) : 0.f;
        float s = v0 + v1;
        float sc = s;
#pragma unroll
        for (int o = 1; o < 32; o <<= 1) {
            float nn = __shfl_up_sync(0xffffffffu, sc, o);
            if (lane >= o) sc += nn;
        }
        if (lane == 31) wsum[warp] = sc;
        __syncthreads();
        if (tid < 32) {
            float v = wsum[tid];
            float scv = v;
#pragma unroll
            for (int o = 1; o < 32; o <<= 1) {
                float nn = __shfl_up_sync(0xffffffffu, scv, o);
                if (tid >= o) scv += nn;
            }
            wsum[tid] = scv - v;
        }
        __syncthreads();
        float base = wsum[warp] + (sc - s);
        g_sufHigh[b * 2049 + e0] = base + v0;
        g_sufHigh[b * 2049 + e1] = base + v0 + v1;
        if (tid == 0) g_sufHigh[b * 2049 + 2048] = 0.f;
    }
}

// ---------------- kernel 4: A values -> packed pk[b][k][n]; smem-staged search ----------------
__global__ void k_aval() {
    __shared__ float sr[2048];
    __shared__ float sufH[2049];
    __shared__ float cumL[2049];
    int tid = threadIdx.x;
    int b = blockIdx.y;
    for (int e = tid; e < 2048; e += 256) sr[e] = g_sortedR[b * 2048 + e];
    for (int e = tid; e < 2049; e += 256) {
        sufH[e] = g_sufHigh[b * 2049 + e];
        cumL[e] = g_cumLowEx[b * 2049 + e];
    }
    __syncthreads();

    int i = blockIdx.x * 256 + tid;
    if (i >= NN) return;
    float l = g_left[b * NN + i];
    float theta = -l;
    int lo = 0, hi = 2048;
    while (lo < hi) {
        int mid = (lo + hi) >> 1;
        if (sr[mid] < theta) lo = mid + 1; else hi = mid;
    }
    float denom = expf(l) * sufH[lo] + expf(0.2f * l) * cumL[lo];
    float inv = 1.0f / denom;
    unsigned* pkb = g_pku + (size_t)b * NK * NN;
    const float* rb = g_right + b * NN;
#pragma unroll
    for (int k = 0; k < NK; k++) {
        int j = g_idx_t[k * NN + i];          // coalesced
        float a1v = g_adj1v_t[k * NN + i];    // coalesced
        float s = l + rb[j];
        float num = (s >= 0.f) ? expf(s) : expf(0.2f * s);
        float aval = num * inv + a1v;
        unsigned u = ((unsigned)__half_as_ushort(__float2half_rn(aval)) << 16) | (unsigned)j;
        pkb[(size_t)k * NN + i] = u;          // coalesced
    }
}

// ---------------- kernel 5: fused 2-step propagation, fp16 slabs + packed pk ----------------
__device__ __forceinline__ void unpack8(uint4 u, float2& f0, float2& f1, float2& f2, float2& f3) {
    f0 = __half22float2(*reinterpret_cast<__half2*>(&u.x));
    f1 = __half22float2(*reinterpret_cast<__half2*>(&u.y));
    f2 = __half22float2(*reinterpret_cast<__half2*>(&u.z));
    f3 = __half22float2(*reinterpret_cast<__half2*>(&u.w));
}

__global__ void __launch_bounds__(PB, 2) k_prop(const float* __restrict__ x) {
    extern __shared__ uint4 smv[];
    uint4* sx = smv;          // x chunk, fp16x8 per node
    uint4* sh = smv + NN;     // h1 chunk

    int tid = threadIdx.x;
    int chunk = blockIdx.x;
    int bt = blockIdx.y;
    int b = bt / NT, t = bt - b * NT;
    int ch0 = chunk * CH;

    const size_t P = (size_t)NT * NN;
    const float* xs = x + ((size_t)(b * NC + ch0) * NT + t) * NN;
    for (int n = tid; n < NN; n += PB) {
        uint4 u;
        *reinterpret_cast<__half2*>(&u.x) = __float22half2_rn(make_float2(xs[n],       xs[P + n]));
        *reinterpret_cast<__half2*>(&u.y) = __float22half2_rn(make_float2(xs[2*P + n], xs[3*P + n]));
        *reinterpret_cast<__half2*>(&u.z) = __float22half2_rn(make_float2(xs[4*P + n], xs[5*P + n]));
        *reinterpret_cast<__half2*>(&u.w) = __float22half2_rn(make_float2(xs[6*P + n], xs[7*P + n]));
        sx[n] = u;
    }
    __syncthreads();

    const unsigned* pkb = g_pku + (size_t)b * NK * NN;

    // ---- step 1: h1 = 0.05 x + 0.95 A x ----
    for (int m = tid; m < NN; m += PB) {
        float2 a0 = {0.f,0.f}, a1 = {0.f,0.f}, a2 = {0.f,0.f}, a3 = {0.f,0.f};
#pragma unroll
        for (int k = 0; k < NK; k++) {
            unsigned u = pkb[(size_t)k * NN + m];       // coalesced LDG.32
            int j = u & 0xFFFFu;
            float av = __half2float(__ushort_as_half((unsigned short)(u >> 16)));
            float2 f0, f1, f2, f3; unpack8(sx[j], f0, f1, f2, f3);
            a0.x += av*f0.x; a0.y += av*f0.y;
            a1.x += av*f1.x; a1.y += av*f1.y;
            a2.x += av*f2.x; a2.y += av*f2.y;
            a3.x += av*f3.x; a3.y += av*f3.y;
        }
        float2 o0, o1, o2, o3; unpack8(sx[m], o0, o1, o2, o3);
        uint4 u;
        *reinterpret_cast<__half2*>(&u.x) = __float22half2_rn(
            make_float2(0.05f*o0.x + 0.95f*a0.x, 0.05f*o0.y + 0.95f*a0.y));
        *reinterpret_cast<__half2*>(&u.y) = __float22half2_rn(
            make_float2(0.05f*o1.x + 0.95f*a1.x, 0.05f*o1.y + 0.95f*a1.y));
        *reinterpret_cast<__half2*>(&u.z) = __float22half2_rn(
            make_float2(0.05f*o2.x + 0.95f*a2.x, 0.05f*o2.y + 0.95f*a2.y));
        *reinterpret_cast<__half2*>(&u.w) = __float22half2_rn(
            make_float2(0.05f*o3.x + 0.95f*a3.x, 0.05f*o3.y + 0.95f*a3.y));
        sh[m] = u;
    }
    __syncthreads();

    // ---- step 2: h2 = 0.05 x + 0.95 A h1 ; fp32 straight to GMEM ----
    float* h2 = g_h2 + ((size_t)bt * NC + ch0) * NN;
    for (int m = tid; m < NN; m += PB) {
        float2 a0 = {0.f,0.f}, a1 = {0.f,0.f}, a2 = {0.f,0.f}, a3 = {0.f,0.f};
#pragma unroll
        for (int k = 0; k < NK; k++) {
            unsigned u = pkb[(size_t)k * NN + m];
            int j = u & 0xFFFFu;
            float av = __half2float(__ushort_as_half((unsigned short)(u >> 16)));
            float2 f0, f1, f2, f3; unpack8(sh[j], f0, f1, f2, f3);
            a0.x += av*f0.x; a0.y += av*f0.y;
            a1.x += av*f1.x; a1.y += av*f1.y;
            a2.x += av*f2.x; a2.y += av*f2.y;
            a3.x += av*f3.x; a3.y += av*f3.y;
        }
        float2 o0, o1, o2, o3; unpack8(sx[m], o0, o1, o2, o3);
        h2[m]              = 0.05f*o0.x + 0.95f*a0.x;
        h2[(size_t)NN + m]   = 0.05f*o0.y + 0.95f*a0.y;
        h2[(size_t)2*NN + m] = 0.05f*o1.x + 0.95f*a1.x;
        h2[(size_t)3*NN + m] = 0.05f*o1.y + 0.95f*a1.y;
        h2[(size_t)4*NN + m] = 0.05f*o2.x + 0.95f*a2.x;
        h2[(size_t)5*NN + m] = 0.05f*o2.y + 0.95f*a2.y;
        h2[(size_t)6*NN + m] = 0.05f*o3.x + 0.95f*a3.x;
        h2[(size_t)7*NN + m] = 0.05f*o3.y + 0.95f*a3.y;
    }
}

// ---------------- kernel 6: output projection ho = W1 h2 + b1 ----------------
__global__ void k_out(float* __restrict__ out, const float* __restrict__ W1,
                      const float* __restrict__ b1) {
    __shared__ float W1s[NC * NC];
    __shared__ float b1s[NC];
    int tid = threadIdx.x;
    for (int i = tid; i < NC * NC; i += 256) W1s[i] = W1[i];
    if (tid < NC) b1s[tid] = b1[tid];
    __syncthreads();
    int bt = blockIdx.y;
    int b = bt / NT, t = bt - b * NT;
    int n = blockIdx.x * 256 + tid;
    if (n >= NN) return;
    float h[NC];
#pragma unroll
    for (int cc = 0; cc < NC; cc++)
        h[cc] = g_h2[((size_t)bt * NC + cc) * NN + n];
#pragma unroll
    for (int o = 0; o < NC; o++) {
        float s = b1s[o];
#pragma unroll
        for (int cc = 0; cc < NC; cc++) s += W1s[o * NC + cc] * h[cc];
        out[((size_t)(b * NC + o) * NT + t) * NN + n] = s;
    }
}

// ---------------- launch ----------------
extern "C" void kernel_launch(void* const* d_in, const int* in_sizes, int n_in,
                              void* d_out, int out_size) {
    const float* x   = (const float*)d_in[0];
    const float* adj = (const float*)d_in[1];
    const float* W1  = (const float*)d_in[2];
    const float* b1  = (const float*)d_in[3];
    const float* W2  = (const float*)d_in[4];
    const float* b2  = (const float*)d_in[5];
    const float* a   = (const float*)d_in[6];
    float* out = (float*)d_out;

    int prop_smem = 2 * NN * (int)sizeof(uint4);    // 64000 B
    cudaFuncSetAttribute(k_prop, cudaFuncAttributeMaxDynamicSharedMemorySize, prop_smem);
    int adjlr_smem = 4 * NN * (int)sizeof(float);   // 32000 B
    cudaFuncSetAttribute(k_adjlr, cudaFuncAttributeMaxDynamicSharedMemorySize, adjlr_smem);

    k_u<<<1, 512>>>(W2, b2, a);
    k_adjlr<<<ADJ_BLOCKS + LR_BLOCKS, 128, adjlr_smem>>>(adj, x);
    k_sort<<<NB, 1024>>>();
    {
        dim3 grid(8, NB);
        k_aval<<<grid, 256>>>();
    }
    {
        dim3 grid(NCHUNK, BT);
        k_prop<<<grid, PB, prop_smem>>>(x);
    }
    {
        dim3 grid(8, BT);
        k_out<<<grid, 256>>>(out, W1, b1);
    }
}

// round 10
// speedup vs baseline: 2.4244x; 1.0050x over previous
#include <cuda_runtime.h>
#include <cuda_fp16.h>
#include <math.h>

#define NB 16
#define NC 32
#define NT 13
#define NN 2000
#define NK 20
#define ND (NT*NC)      // 416
#define BT (NB*NT)      // 208
#define CH 8            // channels per prop chunk (packed as 4 half2 = 16B)
#define NCHUNK (NC/CH)  // 4
#define PB 512          // k_prop block size

#define ADJ_BLOCKS 500  // 4 rows per block
#define LR_BLOCKS  250  // 32000 / 128

// ---------------- scratch (device globals; no allocation allowed) ----------------
__device__ float    g_h2[(size_t)BT*NC*NN];  // h after 2 prop steps, [bt][c][n]
__device__ float    g_left[NB*NN];
__device__ float    g_right[NB*NN];
__device__ int      g_idx_t[NK*NN];          // TRANSPOSED [k][n]
__device__ float    g_adj1v_t[NK*NN];        // TRANSPOSED [k][n]
__device__ unsigned g_pku[(size_t)NB*NK*NN]; // packed {half aval | uint16 idx} at [b][k][n]
__device__ float    g_u1[ND];
__device__ float    g_u2[ND];
__device__ float    g_LR0[2];

// ---------------- kernel 1: u1/u2 = a-slices folded into W2; bias constants ----------------
__global__ void k_u(const float* __restrict__ W2, const float* __restrict__ b2,
                    const float* __restrict__ a) {
    int tid = threadIdx.x;
    if (tid < ND) {
        int t = tid >> 5, c = tid & 31;
        float s1 = 0.f, s2 = 0.f;
        for (int o = 0; o < NC; o++) {
            float w = W2[o * NC + c];
            s1 += a[t * NC + o] * w;
            s2 += a[ND + t * NC + o] * w;
        }
        g_u1[tid] = s1;
        g_u2[tid] = s2;
    } else if (tid == ND) {
        float s = 0.f;
        for (int d = 0; d < ND; d++) s += b2[d & 31] * a[d];
        g_LR0[0] = s;
    } else if (tid == ND + 1) {
        float s = 0.f;
        for (int d = 0; d < ND; d++) s += b2[d & 31] * a[ND + d];
        g_LR0[1] = s;
    }
}

// ---------------- kernel 2: FUSED  [adj relu+norm+topK (top-2 lanes)]  ||  [left/right] ----------------
__global__ void k_adjlr(const float* __restrict__ adj, const float* __restrict__ x) {
    extern __shared__ float dsm[];
    if (blockIdx.x < ADJ_BLOCKS) {
        int warp = threadIdx.x >> 5, lane = threadIdx.x & 31;
        int row = blockIdx.x * 4 + warp;
        if (row >= NN) return;
        float* v = dsm + warp * NN;
        const float* arow = adj + (size_t)row * NN;

        float psum = 0.f;
        float bv1 = -1.f, bv2 = -1.f; int bi1 = 0, bi2 = 0;
        bool valid2 = true;
#pragma unroll 8
        for (int q = 0; q < 63; q++) {
            int e = lane + 32 * q;
            if (e < NN) {
                float xv = arow[e];
                xv = xv > 0.f ? xv : 0.f;
                v[e] = xv;
                psum += xv;
                if (xv > bv1)      { bv2 = bv1; bi2 = bi1; bv1 = xv; bi1 = e; }
                else if (xv > bv2) { bv2 = xv; bi2 = e; }
            }
        }
#pragma unroll
        for (int o = 16; o > 0; o >>= 1) psum += __shfl_xor_sync(0xffffffffu, psum, o);
        float invdeg = 1.0f / psum;

        for (int it = 0; it < NK; it++) {
            float mv = bv1; int mi = bi1;
#pragma unroll
            for (int o = 16; o > 0; o >>= 1) {
                float ov = __shfl_xor_sync(0xffffffffu, mv, o);
                int   oi = __shfl_xor_sync(0xffffffffu, mi, o);
                if (ov > mv || (ov == mv && oi < mi)) { mv = ov; mi = oi; }
            }
            if (lane == 0) {
                g_idx_t[it * NN + row]   = mi;          // transposed write
                g_adj1v_t[it * NN + row] = mv * invdeg;
            }
            if ((mi & 31) == lane) {   // winner lane pops; rescan only if top2 unknown
                v[mi] = -2.0f;
                if (valid2) { bv1 = bv2; bi1 = bi2; valid2 = false; }
                else {
                    bv1 = -1.f; bi1 = 0; bv2 = -1.f; bi2 = 0;
#pragma unroll 8
                    for (int q = 0; q < 63; q++) {
                        int e = lane + 32 * q;
                        if (e < NN) {
                            float xv = v[e];
                            if (xv > bv1)      { bv2 = bv1; bi2 = bi1; bv1 = xv; bi1 = e; }
                            else if (xv > bv2) { bv2 = xv; bi2 = e; }
                        }
                    }
                    valid2 = true;
                }
            }
            __syncwarp();
        }
    } else {
        float* su1 = dsm;
        float* su2 = dsm + ND;
        int tid = threadIdx.x;
        for (int i = tid; i < ND; i += 128) { su1[i] = g_u1[i]; su2[i] = g_u2[i]; }
        __syncthreads();
        int g = (blockIdx.x - ADJ_BLOCKS) * 128 + tid;   // 0..31999
        int b = g / NN, n = g - b * NN;
        const float* xb = x + (size_t)b * NC * NT * NN + n;
        float s1 = 0.f, s2 = 0.f;
#pragma unroll 4
        for (int c = 0; c < NC; c++) {
#pragma unroll
            for (int t = 0; t < NT; t++) {
                float v = xb[(size_t)(c * NT + t) * NN];
                s1 += v * su1[t * NC + c];
                s2 += v * su2[t * NC + c];
            }
        }
        g_left[g]  = s1 + g_LR0[0];
        g_right[g] = s2 + g_LR0[1];
    }
}

// ---------------- kernel 3: FUSED sort + scans + A-value pack (tables never leave smem) ----------------
__global__ void k_sortaval() {
    __shared__ float ss[2048];
    __shared__ float cumL[2049];
    __shared__ float sufH[2049];
    __shared__ float wsum[32];
    int b = blockIdx.x;
    int tid = threadIdx.x;
    int lane = tid & 31, warp = tid >> 5;

    ss[tid]        = (tid < NN)        ? g_right[b * NN + tid]        : INFINITY;
    ss[tid + 1024] = (tid + 1024 < NN) ? g_right[b * NN + tid + 1024] : INFINITY;
    __syncthreads();

    // bitonic ascending; j<32 stages via shfl (element e=tid lives on lane e&31)
    for (int k2 = 2; k2 <= 2048; k2 <<= 1) {
        for (int j = k2 >> 1; j >= 32; j >>= 1) {
#pragma unroll
            for (int r = 0; r < 2; r++) {
                int e = tid + r * 1024;
                int p = e ^ j;
                if (p > e) {
                    bool up = ((e & k2) == 0);
                    float av = ss[e], bvv = ss[p];
                    if ((av > bvv) == up) { ss[e] = bvv; ss[p] = av; }
                }
            }
            __syncthreads();
        }
        int e0 = tid, e1 = tid + 1024;
        float r0 = ss[e0], r1 = ss[e1];
        bool up0 = ((e0 & k2) == 0);
        bool up1 = ((e1 & k2) == 0);
        int jstart = (k2 >= 32) ? 16 : (k2 >> 1);
        for (int j = jstart; j >= 1; j >>= 1) {
            float p0 = __shfl_xor_sync(0xffffffffu, r0, j);
            float p1 = __shfl_xor_sync(0xffffffffu, r1, j);
            bool lo0 = ((e0 & j) == 0);
            bool lo1 = ((e1 & j) == 0);
            r0 = (lo0 == up0) ? fminf(r0, p0) : fmaxf(r0, p0);
            r1 = (lo1 == up1) ? fminf(r1, p1) : fmaxf(r1, p1);
        }
        ss[e0] = r0; ss[e1] = r1;
        __syncthreads();
    }

    // ---- prefix scan of exp(0.2*sorted) -> cumL (exclusive, smem) ----
    {
        int e0 = 2 * tid, e1 = 2 * tid + 1;
        float v0 = (e0 < NN) ? expf(0.2f * ss[e0]) : 0.f;
        float v1 = (e1 < NN) ? expf(0.2f * ss[e1]) : 0.f;
        float s = v0 + v1;
        float sc = s;
#pragma unroll
        for (int o = 1; o < 32; o <<= 1) {
            float nn = __shfl_up_sync(0xffffffffu, sc, o);
            if (lane >= o) sc += nn;
        }
        if (lane == 31) wsum[warp] = sc;
        __syncthreads();
        if (tid < 32) {
            float v = wsum[tid];
            float scv = v;
#pragma unroll
            for (int o = 1; o < 32; o <<= 1) {
                float nn = __shfl_up_sync(0xffffffffu, scv, o);
                if (tid >= o) scv += nn;
            }
            wsum[tid] = scv - v;   // exclusive warp offset
        }
        __syncthreads();
        float base = wsum[warp] + (sc - s);
        cumL[e0 + 1] = base + v0;
        cumL[e1 + 1] = base + v0 + v1;
        if (tid == 0) cumL[0] = 0.f;
        __syncthreads();
    }

    // ---- suffix scan of exp(sorted) -> sufH (smem) ----
    {
        int e0 = 2047 - 2 * tid;      // rev-pos 2t
        int e1 = 2046 - 2 * tid;      // rev-pos 2t+1
        float v0 = (e0 < NN) ? expf(ss[e0]) : 0.f;
        float v1 = (e1 < NN) ? expf(ss[e1]) : 0.f;
        float s = v0 + v1;
        float sc = s;
#pragma unroll
        for (int o = 1; o < 32; o <<= 1) {
            float nn = __shfl_up_sync(0xffffffffu, sc, o);
            if (lane >= o) sc += nn;
        }
        if (lane == 31) wsum[warp] = sc;
        __syncthreads();
        if (tid < 32) {
            float v = wsum[tid];
            float scv = v;
#pragma unroll
            for (int o = 1; o < 32; o <<= 1) {
                float nn = __shfl_up_sync(0xffffffffu, scv, o);
                if (tid >= o) scv += nn;
            }
            wsum[tid] = scv - v;
        }
        __syncthreads();
        float base = wsum[warp] + (sc - s);
        sufH[e0] = base + v0;
        sufH[e1] = base + v0 + v1;
        if (tid == 0) sufH[2048] = 0.f;
        __syncthreads();
    }

    // ---- A values: binary search + pack, straight from smem tables ----
    unsigned* pkb = g_pku + (size_t)b * NK * NN;
    const float* rb = g_right + b * NN;
#pragma unroll
    for (int r = 0; r < 2; r++) {
        int i = tid + r * 1024;
        if (i >= NN) continue;
        float l = g_left[b * NN + i];
        float theta = -l;
        int lo = 0, hi = 2048;
        while (lo < hi) {
            int mid = (lo + hi) >> 1;
            if (ss[mid] < theta) lo = mid + 1; else hi = mid;
        }
        float denom = expf(l) * sufH[lo] + expf(0.2f * l) * cumL[lo];
        float inv = 1.0f / denom;
#pragma unroll
        for (int k = 0; k < NK; k++) {
            int j = g_idx_t[k * NN + i];          // coalesced
            float a1v = g_adj1v_t[k * NN + i];    // coalesced
            float s = l + rb[j];
            float num = (s >= 0.f) ? expf(s) : expf(0.2f * s);
            float aval = num * inv + a1v;
            unsigned u = ((unsigned)__half_as_ushort(__float2half_rn(aval)) << 16) | (unsigned)j;
            pkb[(size_t)k * NN + i] = u;          // coalesced
        }
    }
}

// ---------------- kernel 4: fused 2-step propagation, fp16 slabs + packed pk ----------------
__device__ __forceinline__ void unpack8(uint4 u, float2& f0, float2& f1, float2& f2, float2& f3) {
    f0 = __half22float2(*reinterpret_cast<__half2*>(&u.x));
    f1 = __half22float2(*reinterpret_cast<__half2*>(&u.y));
    f2 = __half22float2(*reinterpret_cast<__half2*>(&u.z));
    f3 = __half22float2(*reinterpret_cast<__half2*>(&u.w));
}

__global__ void __launch_bounds__(PB, 2) k_prop(const float* __restrict__ x) {
    extern __shared__ uint4 smv[];
    uint4* sx = smv;          // x chunk, fp16x8 per node
    uint4* sh = smv + NN;     // h1 chunk

    int tid = threadIdx.x;
    int chunk = blockIdx.x;
    int bt = blockIdx.y;
    int b = bt / NT, t = bt - b * NT;
    int ch0 = chunk * CH;

    const size_t P = (size_t)NT * NN;
    const float* xs = x + ((size_t)(b * NC + ch0) * NT + t) * NN;
    for (int n = tid; n < NN; n += PB) {
        uint4 u;
        *reinterpret_cast<__half2*>(&u.x) = __float22half2_rn(make_float2(xs[n],       xs[P + n]));
        *reinterpret_cast<__half2*>(&u.y) = __float22half2_rn(make_float2(xs[2*P + n], xs[3*P + n]));
        *reinterpret_cast<__half2*>(&u.z) = __float22half2_rn(make_float2(xs[4*P + n], xs[5*P + n]));
        *reinterpret_cast<__half2*>(&u.w) = __float22half2_rn(make_float2(xs[6*P + n], xs[7*P + n]));
        sx[n] = u;
    }
    __syncthreads();

    const unsigned* pkb = g_pku + (size_t)b * NK * NN;

    // ---- step 1: h1 = 0.05 x + 0.95 A x ----
    for (int m = tid; m < NN; m += PB) {
        float2 a0 = {0.f,0.f}, a1 = {0.f,0.f}, a2 = {0.f,0.f}, a3 = {0.f,0.f};
#pragma unroll
        for (int k = 0; k < NK; k++) {
            unsigned u = pkb[(size_t)k * NN + m];       // coalesced LDG.32
            int j = u & 0xFFFFu;
            float av = __half2float(__ushort_as_half((unsigned short)(u >> 16)));
            float2 f0, f1, f2, f3; unpack8(sx[j], f0, f1, f2, f3);
            a0.x += av*f0.x; a0.y += av*f0.y;
            a1.x += av*f1.x; a1.y += av*f1.y;
            a2.x += av*f2.x; a2.y += av*f2.y;
            a3.x += av*f3.x; a3.y += av*f3.y;
        }
        float2 o0, o1, o2, o3; unpack8(sx[m], o0, o1, o2, o3);
        uint4 u;
        *reinterpret_cast<__half2*>(&u.x) = __float22half2_rn(
            make_float2(0.05f*o0.x + 0.95f*a0.x, 0.05f*o0.y + 0.95f*a0.y));
        *reinterpret_cast<__half2*>(&u.y) = __float22half2_rn(
            make_float2(0.05f*o1.x + 0.95f*a1.x, 0.05f*o1.y + 0.95f*a1.y));
        *reinterpret_cast<__half2*>(&u.z) = __float22half2_rn(
            make_float2(0.05f*o2.x + 0.95f*a2.x, 0.05f*o2.y + 0.95f*a2.y));
        *reinterpret_cast<__half2*>(&u.w) = __float22half2_rn(
            make_float2(0.05f*o3.x + 0.95f*a3.x, 0.05f*o3.y + 0.95f*a3.y));
        sh[m] = u;
    }
    __syncthreads();

    // ---- step 2: h2 = 0.05 x + 0.95 A h1 ; fp32 straight to GMEM ----
    float* h2 = g_h2 + ((size_t)bt * NC + ch0) * NN;
    for (int m = tid; m < NN; m += PB) {
        float2 a0 = {0.f,0.f}, a1 = {0.f,0.f}, a2 = {0.f,0.f}, a3 = {0.f,0.f};
#pragma unroll
        for (int k = 0; k < NK; k++) {
            unsigned u = pkb[(size_t)k * NN + m];
            int j = u & 0xFFFFu;
            float av = __half2float(__ushort_as_half((unsigned short)(u >> 16)));
            float2 f0, f1, f2, f3; unpack8(sh[j], f0, f1, f2, f3);
            a0.x += av*f0.x; a0.y += av*f0.y;
            a1.x += av*f1.x; a1.y += av*f1.y;
            a2.x += av*f2.x; a2.y += av*f2.y;
            a3.x += av*f3.x; a3.y += av*f3.y;
        }
        float2 o0, o1, o2, o3; unpack8(sx[m], o0, o1, o2, o3);
        h2[m]              = 0.05f*o0.x + 0.95f*a0.x;
        h2[(size_t)NN + m]   = 0.05f*o0.y + 0.95f*a0.y;
        h2[(size_t)2*NN + m] = 0.05f*o1.x + 0.95f*a1.x;
        h2[(size_t)3*NN + m] = 0.05f*o1.y + 0.95f*a1.y;
        h2[(size_t)4*NN + m] = 0.05f*o2.x + 0.95f*a2.x;
        h2[(size_t)5*NN + m] = 0.05f*o2.y + 0.95f*a2.y;
        h2[(size_t)6*NN + m] = 0.05f*o3.x + 0.95f*a3.x;
        h2[(size_t)7*NN + m] = 0.05f*o3.y + 0.95f*a3.y;
    }
}

// ---------------- kernel 5: output projection ho = W1 h2 + b1 ----------------
__global__ void k_out(float* __restrict__ out, const float* __restrict__ W1,
                      const float* __restrict__ b1) {
    __shared__ float W1s[NC * NC];
    __shared__ float b1s[NC];
    int tid = threadIdx.x;
    for (int i = tid; i < NC * NC; i += 256) W1s[i] = W1[i];
    if (tid < NC) b1s[tid] = b1[tid];
    __syncthreads();
    int bt = blockIdx.y;
    int b = bt / NT, t = bt - b * NT;
    int n = blockIdx.x * 256 + tid;
    if (n >= NN) return;
    float h[NC];
#pragma unroll
    for (int cc = 0; cc < NC; cc++)
        h[cc] = g_h2[((size_t)bt * NC + cc) * NN + n];
#pragma unroll
    for (int o = 0; o < NC; o++) {
        float s = b1s[o];
#pragma unroll
        for (int cc = 0; cc < NC; cc++) s += W1s[o * NC + cc] * h[cc];
        out[((size_t)(b * NC + o) * NT + t) * NN + n] = s;
    }
}

// ---------------- launch ----------------
extern "C" void kernel_launch(void* const* d_in, const int* in_sizes, int n_in,
                              void* d_out, int out_size) {
    const float* x   = (const float*)d_in[0];
    const float* adj = (const float*)d_in[1];
    const float* W1  = (const float*)d_in[2];
    const float* b1  = (const float*)d_in[3];
    const float* W2  = (const float*)d_in[4];
    const float* b2  = (const float*)d_in[5];
    const float* a   = (const float*)d_in[6];
    float* out = (float*)d_out;

    int prop_smem = 2 * NN * (int)sizeof(uint4);    // 64000 B
    cudaFuncSetAttribute(k_prop, cudaFuncAttributeMaxDynamicSharedMemorySize, prop_smem);
    int adjlr_smem = 4 * NN * (int)sizeof(float);   // 32000 B
    cudaFuncSetAttribute(k_adjlr, cudaFuncAttributeMaxDynamicSharedMemorySize, adjlr_smem);

    k_u<<<1, 512>>>(W2, b2, a);
    k_adjlr<<<ADJ_BLOCKS + LR_BLOCKS, 128, adjlr_smem>>>(adj, x);
    k_sortaval<<<NB, 1024>>>();
    {
        dim3 grid(NCHUNK, BT);
        k_prop<<<grid, PB, prop_smem>>>(x);
    }
    {
        dim3 grid(8, BT);
        k_out<<<grid, 256>>>(out, W1, b1);
    }
}

// round 11
// speedup vs baseline: 2.7225x; 1.1230x over previous
#include <cuda_runtime.h>
#include <cuda_fp16.h>
#include <math.h>

#define NB 16
#define NC 32
#define NT 13
#define NN 2000
#define NK 20
#define ND (NT*NC)      // 416
#define BT (NB*NT)      // 208
#define CH 8            // channels per prop chunk (packed as 4 half2 = 16B)
#define NCHUNK (NC/CH)  // 4
#define PB 512          // k_prop block size

#define ADJ_BLOCKS 500  // 4 rows per block
#define LR_BLOCKS  250  // 32000 / 128

// ---------------- scratch (device globals; no allocation allowed) ----------------
__device__ __half   g_h2h[(size_t)BT*NC*NN]; // h after 2 prop steps, fp16, [bt][c][n]
__device__ float    g_left[NB*NN];
__device__ float    g_right[NB*NN];
__device__ int      g_idx_t[NK*NN];          // TRANSPOSED [k][n]
__device__ float    g_adj1v_t[NK*NN];        // TRANSPOSED [k][n]
__device__ unsigned g_pku[(size_t)NB*NK*NN]; // packed {half aval | uint16 idx} at [b][k][n]
__device__ float    g_sortedR[NB*2048];
__device__ float    g_sufHigh[NB*2049];
__device__ float    g_cumLowEx[NB*2049];

// ---------------- kernel 1: FUSED [adj topK (float4 scan, top-2 lanes)] || [u + left/right] ----------------
__global__ void k_adjlr(const float* __restrict__ adj, const float* __restrict__ x,
                        const float* __restrict__ W2, const float* __restrict__ b2,
                        const float* __restrict__ a) {
    extern __shared__ float dsm[];
    if (blockIdx.x < ADJ_BLOCKS) {
        int warp = threadIdx.x >> 5, lane = threadIdx.x & 31;
        int row = blockIdx.x * 4 + warp;
        if (row >= NN) return;
        float* v = dsm + warp * NN;
        const float4* arow4 = reinterpret_cast<const float4*>(adj + (size_t)row * NN);

        float psum = 0.f;
        float bv1 = -1.f, bv2 = -1.f; int bi1 = 0, bi2 = 0;
        bool valid2 = true;
#pragma unroll 4
        for (int q = 0; q < 16; q++) {
            int e4 = lane + 32 * q;
            if (e4 < NN / 4) {
                float4 xv4 = arow4[e4];
                float vv[4] = {xv4.x, xv4.y, xv4.z, xv4.w};
#pragma unroll
                for (int s = 0; s < 4; s++) {
                    float xv = vv[s] > 0.f ? vv[s] : 0.f;
                    int e = 4 * e4 + s;
                    v[e] = xv;
                    psum += xv;
                    if (xv > bv1)      { bv2 = bv1; bi2 = bi1; bv1 = xv; bi1 = e; }
                    else if (xv > bv2) { bv2 = xv; bi2 = e; }
                }
            }
        }
#pragma unroll
        for (int o = 16; o > 0; o >>= 1) psum += __shfl_xor_sync(0xffffffffu, psum, o);
        float invdeg = 1.0f / psum;

        for (int it = 0; it < NK; it++) {
            float mv = bv1; int mi = bi1;
#pragma unroll
            for (int o = 16; o > 0; o >>= 1) {
                float ov = __shfl_xor_sync(0xffffffffu, mv, o);
                int   oi = __shfl_xor_sync(0xffffffffu, mi, o);
                if (ov > mv || (ov == mv && oi < mi)) { mv = ov; mi = oi; }
            }
            if (lane == 0) {
                g_idx_t[it * NN + row]   = mi;
                g_adj1v_t[it * NN + row] = mv * invdeg;
            }
            if ((mi & 31) == ((mi >> 2) & 31 ? (mi >> 2) & 31 : (mi >> 2) & 31)) {}  // (no-op)
            // owner lane of element e is (e/4) % 32
            if (((mi >> 2) & 31) == lane) {
                v[mi] = -2.0f;
                if (valid2) { bv1 = bv2; bi1 = bi2; valid2 = false; }
                else {
                    bv1 = -1.f; bi1 = 0; bv2 = -1.f; bi2 = 0;
                    const float4* v4 = reinterpret_cast<const float4*>(v);
#pragma unroll 4
                    for (int q = 0; q < 16; q++) {
                        int e4 = lane + 32 * q;
                        if (e4 < NN / 4) {
                            float4 xv4 = v4[e4];
                            float vv[4] = {xv4.x, xv4.y, xv4.z, xv4.w};
#pragma unroll
                            for (int s = 0; s < 4; s++) {
                                float xv = vv[s];
                                int e = 4 * e4 + s;
                                if (xv > bv1)      { bv2 = bv1; bi2 = bi1; bv1 = xv; bi1 = e; }
                                else if (xv > bv2) { bv2 = xv; bi2 = e; }
                            }
                        }
                    }
                    valid2 = true;
                }
            }
            __syncwarp();
        }
    } else {
        float* su1 = dsm;
        float* su2 = dsm + ND;
        float* red = dsm + 2 * ND;     // 8 floats scratch
        int tid = threadIdx.x;
        int lane = tid & 31, warp = tid >> 5;
        // compute u1/u2 inline
        for (int i = tid; i < ND; i += 128) {
            int t = i >> 5, c = i & 31;
            float s1 = 0.f, s2 = 0.f;
            for (int o = 0; o < NC; o++) {
                float w = W2[o * NC + c];
                s1 += a[t * NC + o] * w;
                s2 += a[ND + t * NC + o] * w;
            }
            su1[i] = s1; su2[i] = s2;
        }
        // LR0 constants
        float p1 = 0.f, p2 = 0.f;
        for (int d = tid; d < ND; d += 128) {
            float bb = b2[d & 31];
            p1 += bb * a[d];
            p2 += bb * a[ND + d];
        }
#pragma unroll
        for (int o = 16; o > 0; o >>= 1) {
            p1 += __shfl_xor_sync(0xffffffffu, p1, o);
            p2 += __shfl_xor_sync(0xffffffffu, p2, o);
        }
        if (lane == 0) { red[warp] = p1; red[4 + warp] = p2; }
        __syncthreads();
        float LR0a = red[0] + red[1] + red[2] + red[3];
        float LR0b = red[4] + red[5] + red[6] + red[7];

        int g = (blockIdx.x - ADJ_BLOCKS) * 128 + tid;   // 0..31999
        int b = g / NN, n = g - b * NN;
        const float* xb = x + (size_t)b * NC * NT * NN + n;
        float s1 = 0.f, s2 = 0.f;
#pragma unroll 4
        for (int c = 0; c < NC; c++) {
#pragma unroll
            for (int t = 0; t < NT; t++) {
                float v = xb[(size_t)(c * NT + t) * NN];
                s1 += v * su1[t * NC + c];
                s2 += v * su2[t * NC + c];
            }
        }
        g_left[g]  = s1 + LR0a;
        g_right[g] = s2 + LR0b;
    }
}

// ---------------- kernel 2: sort (warp-shfl bitonic) + shfl scans -> GMEM tables ----------------
__global__ void k_sort() {
    __shared__ float ss[2048];
    __shared__ float wsum[32];
    int b = blockIdx.x;
    int tid = threadIdx.x;
    int lane = tid & 31, warp = tid >> 5;

    ss[tid]        = (tid < NN)        ? g_right[b * NN + tid]        : INFINITY;
    ss[tid + 1024] = (tid + 1024 < NN) ? g_right[b * NN + tid + 1024] : INFINITY;
    __syncthreads();

    for (int k2 = 2; k2 <= 2048; k2 <<= 1) {
        for (int j = k2 >> 1; j >= 32; j >>= 1) {
#pragma unroll
            for (int r = 0; r < 2; r++) {
                int e = tid + r * 1024;
                int p = e ^ j;
                if (p > e) {
                    bool up = ((e & k2) == 0);
                    float av = ss[e], bvv = ss[p];
                    if ((av > bvv) == up) { ss[e] = bvv; ss[p] = av; }
                }
            }
            __syncthreads();
        }
        int e0 = tid, e1 = tid + 1024;
        float r0 = ss[e0], r1 = ss[e1];
        bool up0 = ((e0 & k2) == 0);
        bool up1 = ((e1 & k2) == 0);
        int jstart = (k2 >= 32) ? 16 : (k2 >> 1);
        for (int j = jstart; j >= 1; j >>= 1) {
            float p0 = __shfl_xor_sync(0xffffffffu, r0, j);
            float p1 = __shfl_xor_sync(0xffffffffu, r1, j);
            bool lo0 = ((e0 & j) == 0);
            bool lo1 = ((e1 & j) == 0);
            r0 = (lo0 == up0) ? fminf(r0, p0) : fmaxf(r0, p0);
            r1 = (lo1 == up1) ? fminf(r1, p1) : fmaxf(r1, p1);
        }
        ss[e0] = r0; ss[e1] = r1;
        __syncthreads();
    }

    g_sortedR[b * 2048 + tid]        = ss[tid];
    g_sortedR[b * 2048 + tid + 1024] = ss[tid + 1024];

    // prefix scan of exp(0.2*sorted)
    {
        int e0 = 2 * tid, e1 = 2 * tid + 1;
        float v0 = (e0 < NN) ? expf(0.2f * ss[e0]) : 0.f;
        float v1 = (e1 < NN) ? expf(0.2f * ss[e1]) : 0.f;
        float s = v0 + v1;
        float sc = s;
#pragma unroll
        for (int o = 1; o < 32; o <<= 1) {
            float nn = __shfl_up_sync(0xffffffffu, sc, o);
            if (lane >= o) sc += nn;
        }
        if (lane == 31) wsum[warp] = sc;
        __syncthreads();
        if (tid < 32) {
            float v = wsum[tid];
            float scv = v;
#pragma unroll
            for (int o = 1; o < 32; o <<= 1) {
                float nn = __shfl_up_sync(0xffffffffu, scv, o);
                if (tid >= o) scv += nn;
            }
            wsum[tid] = scv - v;
        }
        __syncthreads();
        float base = wsum[warp] + (sc - s);
        g_cumLowEx[b * 2049 + e0 + 1] = base + v0;
        g_cumLowEx[b * 2049 + e1 + 1] = base + v0 + v1;
        if (tid == 0) g_cumLowEx[b * 2049] = 0.f;
        __syncthreads();
    }

    // suffix scan of exp(sorted)
    {
        int e0 = 2047 - 2 * tid;
        int e1 = 2046 - 2 * tid;
        float v0 = (e0 < NN) ? expf(ss[e0]) : 0.f;
        float v1 = (e1 < NN) ? expf(ss[e1]) : 0.f;
        float s = v0 + v1;
        float sc = s;
#pragma unroll
        for (int o = 1; o < 32; o <<= 1) {
            float nn = __shfl_up_sync(0xffffffffu, sc, o);
            if (lane >= o) sc += nn;
        }
        if (lane == 31) wsum[warp] = sc;
        __syncthreads();
        if (tid < 32) {
            float v = wsum[tid];
            float scv = v;
#pragma unroll
            for (int o = 1; o < 32; o <<= 1) {
                float nn = __shfl_up_sync(0xffffffffu, scv, o);
                if (tid >= o) scv += nn;
            }
            wsum[tid] = scv - v;
        }
        __syncthreads();
        float base = wsum[warp] + (sc - s);
        g_sufHigh[b * 2049 + e0] = base + v0;
        g_sufHigh[b * 2049 + e1] = base + v0 + v1;
        if (tid == 0) g_sufHigh[b * 2049 + 2048] = 0.f;
    }
}

// ---------------- kernel 3: wide A-value pack; right[] staged in smem, tables via L2 ----------------
__global__ void k_aval() {
    __shared__ float srb[NN];
    int tid = threadIdx.x;
    int b = blockIdx.y;
    const float* rb = g_right + b * NN;
    for (int e = tid; e < NN; e += 256) srb[e] = rb[e];
    __syncthreads();

    int i = blockIdx.x * 256 + tid;
    if (i >= NN) return;
    float l = g_left[b * NN + i];
    float theta = -l;
    const float* sr = g_sortedR + b * 2048;
    int lo = 0, hi = 2048;
    while (lo < hi) {
        int mid = (lo + hi) >> 1;
        if (sr[mid] < theta) lo = mid + 1; else hi = mid;
    }
    float denom = expf(l) * g_sufHigh[b * 2049 + lo]
                + expf(0.2f * l) * g_cumLowEx[b * 2049 + lo];
    float inv = 1.0f / denom;
    unsigned* pkb = g_pku + (size_t)b * NK * NN;
#pragma unroll
    for (int k = 0; k < NK; k++) {
        int j = g_idx_t[k * NN + i];          // coalesced
        float a1v = g_adj1v_t[k * NN + i];    // coalesced
        float s = l + srb[j];
        float num = (s >= 0.f) ? expf(s) : expf(0.2f * s);
        float aval = num * inv + a1v;
        unsigned u = ((unsigned)__half_as_ushort(__float2half_rn(aval)) << 16) | (unsigned)j;
        pkb[(size_t)k * NN + i] = u;          // coalesced
    }
}

// ---------------- kernel 4: fused 2-step propagation, fp16 slabs + packed pk ----------------
__device__ __forceinline__ void unpack8(uint4 u, float2& f0, float2& f1, float2& f2, float2& f3) {
    f0 = __half22float2(*reinterpret_cast<__half2*>(&u.x));
    f1 = __half22float2(*reinterpret_cast<__half2*>(&u.y));
    f2 = __half22float2(*reinterpret_cast<__half2*>(&u.z));
    f3 = __half22float2(*reinterpret_cast<__half2*>(&u.w));
}

__global__ void __launch_bounds__(PB, 2) k_prop(const float* __restrict__ x) {
    extern __shared__ uint4 smv[];
    uint4* sx = smv;          // x chunk, fp16x8 per node
    uint4* sh = smv + NN;     // h1 chunk

    int tid = threadIdx.x;
    int chunk = blockIdx.x;
    int bt = blockIdx.y;
    int b = bt / NT, t = bt - b * NT;
    int ch0 = chunk * CH;

    const size_t P = (size_t)NT * NN;
    const float* xs = x + ((size_t)(b * NC + ch0) * NT + t) * NN;
    for (int n = tid; n < NN; n += PB) {
        uint4 u;
        *reinterpret_cast<__half2*>(&u.x) = __float22half2_rn(make_float2(xs[n],       xs[P + n]));
        *reinterpret_cast<__half2*>(&u.y) = __float22half2_rn(make_float2(xs[2*P + n], xs[3*P + n]));
        *reinterpret_cast<__half2*>(&u.z) = __float22half2_rn(make_float2(xs[4*P + n], xs[5*P + n]));
        *reinterpret_cast<__half2*>(&u.w) = __float22half2_rn(make_float2(xs[6*P + n], xs[7*P + n]));
        sx[n] = u;
    }
    __syncthreads();

    const unsigned* pkb = g_pku + (size_t)b * NK * NN;

    // ---- step 1: h1 = 0.05 x + 0.95 A x ----
    for (int m = tid; m < NN; m += PB) {
        float2 a0 = {0.f,0.f}, a1 = {0.f,0.f}, a2 = {0.f,0.f}, a3 = {0.f,0.f};
#pragma unroll
        for (int k = 0; k < NK; k++) {
            unsigned u = pkb[(size_t)k * NN + m];       // coalesced LDG.32
            int j = u & 0xFFFFu;
            float av = __half2float(__ushort_as_half((unsigned short)(u >> 16)));
            float2 f0, f1, f2, f3; unpack8(sx[j], f0, f1, f2, f3);
            a0.x += av*f0.x; a0.y += av*f0.y;
            a1.x += av*f1.x; a1.y += av*f1.y;
            a2.x += av*f2.x; a2.y += av*f2.y;
            a3.x += av*f3.x; a3.y += av*f3.y;
        }
        float2 o0, o1, o2, o3; unpack8(sx[m], o0, o1, o2, o3);
        uint4 u;
        *reinterpret_cast<__half2*>(&u.x) = __float22half2_rn(
            make_float2(0.05f*o0.x + 0.95f*a0.x, 0.05f*o0.y + 0.95f*a0.y));
        *reinterpret_cast<__half2*>(&u.y) = __float22half2_rn(
            make_float2(0.05f*o1.x + 0.95f*a1.x, 0.05f*o1.y + 0.95f*a1.y));
        *reinterpret_cast<__half2*>(&u.z) = __float22half2_rn(
            make_float2(0.05f*o2.x + 0.95f*a2.x, 0.05f*o2.y + 0.95f*a2.y));
        *reinterpret_cast<__half2*>(&u.w) = __float22half2_rn(
            make_float2(0.05f*o3.x + 0.95f*a3.x, 0.05f*o3.y + 0.95f*a3.y));
        sh[m] = u;
    }
    __syncthreads();

    // ---- step 2: h2 = 0.05 x + 0.95 A h1 ; store fp16 planes ----
    __half* h2 = g_h2h + ((size_t)bt * NC + ch0) * NN;
    for (int m = tid; m < NN; m += PB) {
        float2 a0 = {0.f,0.f}, a1 = {0.f,0.f}, a2 = {0.f,0.f}, a3 = {0.f,0.f};
#pragma unroll
        for (int k = 0; k < NK; k++) {
            unsigned u = pkb[(size_t)k * NN + m];
            int j = u & 0xFFFFu;
            float av = __half2float(__ushort_as_half((unsigned short)(u >> 16)));
            float2 f0, f1, f2, f3; unpack8(sh[j], f0, f1, f2, f3);
            a0.x += av*f0.x; a0.y += av*f0.y;
            a1.x += av*f1.x; a1.y += av*f1.y;
            a2.x += av*f2.x; a2.y += av*f2.y;
            a3.x += av*f3.x; a3.y += av*f3.y;
        }
        float2 o0, o1, o2, o3; unpack8(sx[m], o0, o1, o2, o3);
        h2[m]              = __float2half_rn(0.05f*o0.x + 0.95f*a0.x);
        h2[(size_t)NN + m]   = __float2half_rn(0.05f*o0.y + 0.95f*a0.y);
        h2[(size_t)2*NN + m] = __float2half_rn(0.05f*o1.x + 0.95f*a1.x);
        h2[(size_t)3*NN + m] = __float2half_rn(0.05f*o1.y + 0.95f*a1.y);
        h2[(size_t)4*NN + m] = __float2half_rn(0.05f*o2.x + 0.95f*a2.x);
        h2[(size_t)5*NN + m] = __float2half_rn(0.05f*o2.y + 0.95f*a2.y);
        h2[(size_t)6*NN + m] = __float2half_rn(0.05f*o3.x + 0.95f*a3.x);
        h2[(size_t)7*NN + m] = __float2half_rn(0.05f*o3.y + 0.95f*a3.y);
    }
}

// ---------------- kernel 5: output projection ho = W1 h2 + b1 (h2 fp16 in) ----------------
__global__ void k_out(float* __restrict__ out, const float* __restrict__ W1,
                      const float* __restrict__ b1) {
    __shared__ float W1s[NC * NC];
    __shared__ float b1s[NC];
    int tid = threadIdx.x;
    for (int i = tid; i < NC * NC; i += 256) W1s[i] = W1[i];
    if (tid < NC) b1s[tid] = b1[tid];
    __syncthreads();
    int bt = blockIdx.y;
    int b = bt / NT, t = bt - b * NT;
    int n = blockIdx.x * 256 + tid;
    if (n >= NN) return;
    const __half* hb = g_h2h + (size_t)bt * NC * NN;
    float h[NC];
#pragma unroll
    for (int cc = 0; cc < NC; cc++)
        h[cc] = __half2float(hb[(size_t)cc * NN + n]);
#pragma unroll
    for (int o = 0; o < NC; o++) {
        float s = b1s[o];
#pragma unroll
        for (int cc = 0; cc < NC; cc++) s += W1s[o * NC + cc] * h[cc];
        out[((size_t)(b * NC + o) * NT + t) * NN + n] = s;
    }
}

// ---------------- launch ----------------
extern "C" void kernel_launch(void* const* d_in, const int* in_sizes, int n_in,
                              void* d_out, int out_size) {
    const float* x   = (const float*)d_in[0];
    const float* adj = (const float*)d_in[1];
    const float* W1  = (const float*)d_in[2];
    const float* b1  = (const float*)d_in[3];
    const float* W2  = (const float*)d_in[4];
    const float* b2  = (const float*)d_in[5];
    const float* a   = (const float*)d_in[6];
    float* out = (float*)d_out;

    int prop_smem = 2 * NN * (int)sizeof(uint4);    // 64000 B
    cudaFuncSetAttribute(k_prop, cudaFuncAttributeMaxDynamicSharedMemorySize, prop_smem);
    int adjlr_smem = 4 * NN * (int)sizeof(float);   // 32000 B
    cudaFuncSetAttribute(k_adjlr, cudaFuncAttributeMaxDynamicSharedMemorySize, adjlr_smem);

    k_adjlr<<<ADJ_BLOCKS + LR_BLOCKS, 128, adjlr_smem>>>(adj, x, W2, b2, a);
    k_sort<<<NB, 1024>>>();
    {
        dim3 grid(8, NB);
        k_aval<<<grid, 256>>>();
    }
    {
        dim3 grid(NCHUNK, BT);
        k_prop<<<grid, PB, prop_smem>>>(x);
    }
    {
        dim3 grid(8, BT);
        k_out<<<grid, 256>>>(out, W1, b1);
    }
}

// round 12
// speedup vs baseline: 2.7535x; 1.0114x over previous
#include <cuda_runtime.h>
#include <cuda_fp16.h>
#include <math.h>

#define NB 16
#define NC 32
#define NT 13
#define NN 2000
#define NK 20
#define ND (NT*NC)      // 416
#define BT (NB*NT)      // 208
#define CH 8            // channels per prop chunk (packed as 4 half2 = 16B)
#define NCHUNK (NC/CH)  // 4
#define PB 512          // k_prop block size

#define ADJ_BLOCKS 500  // 4 rows per block
#define LR_BLOCKS  250  // 32000 / 128

// ---------------- scratch (device globals; no allocation allowed) ----------------
__device__ __half   g_h2h[(size_t)BT*NC*NN]; // h after 2 prop steps, fp16, [bt][c][n]
__device__ float    g_left[NB*NN];
__device__ float    g_right[NB*NN];
__device__ int      g_idx_t[NK*NN];          // TRANSPOSED [k][n]
__device__ float    g_adj1v_t[NK*NN];        // TRANSPOSED [k][n]
__device__ unsigned g_pku[(size_t)NB*NK*NN]; // packed {half aval | uint16 idx} at [b][k][n]

// ---------------- kernel 1: FUSED [adj topK (float4 scan, top-2 lanes)] || [u + left/right] ----------------
__global__ void k_adjlr(const float* __restrict__ adj, const float* __restrict__ x,
                        const float* __restrict__ W2, const float* __restrict__ b2,
                        const float* __restrict__ a) {
    extern __shared__ float dsm[];
    if (blockIdx.x < ADJ_BLOCKS) {
        int warp = threadIdx.x >> 5, lane = threadIdx.x & 31;
        int row = blockIdx.x * 4 + warp;
        if (row >= NN) return;
        float* v = dsm + warp * NN;
        const float4* arow4 = reinterpret_cast<const float4*>(adj + (size_t)row * NN);

        float psum = 0.f;
        float bv1 = -1.f, bv2 = -1.f; int bi1 = 0, bi2 = 0;
        bool valid2 = true;
#pragma unroll 4
        for (int q = 0; q < 16; q++) {
            int e4 = lane + 32 * q;
            if (e4 < NN / 4) {
                float4 xv4 = arow4[e4];
                float vv[4] = {xv4.x, xv4.y, xv4.z, xv4.w};
#pragma unroll
                for (int s = 0; s < 4; s++) {
                    float xv = vv[s] > 0.f ? vv[s] : 0.f;
                    int e = 4 * e4 + s;
                    v[e] = xv;
                    psum += xv;
                    if (xv > bv1)      { bv2 = bv1; bi2 = bi1; bv1 = xv; bi1 = e; }
                    else if (xv > bv2) { bv2 = xv; bi2 = e; }
                }
            }
        }
#pragma unroll
        for (int o = 16; o > 0; o >>= 1) psum += __shfl_xor_sync(0xffffffffu, psum, o);
        float invdeg = 1.0f / psum;

        for (int it = 0; it < NK; it++) {
            float mv = bv1; int mi = bi1;
#pragma unroll
            for (int o = 16; o > 0; o >>= 1) {
                float ov = __shfl_xor_sync(0xffffffffu, mv, o);
                int   oi = __shfl_xor_sync(0xffffffffu, mi, o);
                if (ov > mv || (ov == mv && oi < mi)) { mv = ov; mi = oi; }
            }
            if (lane == 0) {
                g_idx_t[it * NN + row]   = mi;
                g_adj1v_t[it * NN + row] = mv * invdeg;
            }
            // owner lane of element e is (e/4) % 32
            if (((mi >> 2) & 31) == lane) {
                v[mi] = -2.0f;
                if (valid2) { bv1 = bv2; bi1 = bi2; valid2 = false; }
                else {
                    bv1 = -1.f; bi1 = 0; bv2 = -1.f; bi2 = 0;
                    const float4* v4 = reinterpret_cast<const float4*>(v);
#pragma unroll 4
                    for (int q = 0; q < 16; q++) {
                        int e4 = lane + 32 * q;
                        if (e4 < NN / 4) {
                            float4 xv4 = v4[e4];
                            float vv[4] = {xv4.x, xv4.y, xv4.z, xv4.w};
#pragma unroll
                            for (int s = 0; s < 4; s++) {
                                float xv = vv[s];
                                int e = 4 * e4 + s;
                                if (xv > bv1)      { bv2 = bv1; bi2 = bi1; bv1 = xv; bi1 = e; }
                                else if (xv > bv2) { bv2 = xv; bi2 = e; }
                            }
                        }
                    }
                    valid2 = true;
                }
            }
            __syncwarp();
        }
    } else {
        float* su1 = dsm;
        float* su2 = dsm + ND;
        float* red = dsm + 2 * ND;     // 8 floats scratch
        int tid = threadIdx.x;
        int lane = tid & 31, warp = tid >> 5;
        // compute u1/u2 inline
        for (int i = tid; i < ND; i += 128) {
            int t = i >> 5, c = i & 31;
            float s1 = 0.f, s2 = 0.f;
            for (int o = 0; o < NC; o++) {
                float w = W2[o * NC + c];
                s1 += a[t * NC + o] * w;
                s2 += a[ND + t * NC + o] * w;
            }
            su1[i] = s1; su2[i] = s2;
        }
        // LR0 constants
        float p1 = 0.f, p2 = 0.f;
        for (int d = tid; d < ND; d += 128) {
            float bb = b2[d & 31];
            p1 += bb * a[d];
            p2 += bb * a[ND + d];
        }
#pragma unroll
        for (int o = 16; o > 0; o >>= 1) {
            p1 += __shfl_xor_sync(0xffffffffu, p1, o);
            p2 += __shfl_xor_sync(0xffffffffu, p2, o);
        }
        if (lane == 0) { red[warp] = p1; red[4 + warp] = p2; }
        __syncthreads();
        float LR0a = red[0] + red[1] + red[2] + red[3];
        float LR0b = red[4] + red[5] + red[6] + red[7];

        int g = (blockIdx.x - ADJ_BLOCKS) * 128 + tid;   // 0..31999
        int b = g / NN, n = g - b * NN;
        const float* xb = x + (size_t)b * NC * NT * NN + n;
        float s1 = 0.f, s2 = 0.f;
#pragma unroll 4
        for (int c = 0; c < NC; c++) {
#pragma unroll
            for (int t = 0; t < NT; t++) {
                float v = xb[(size_t)(c * NT + t) * NN];
                s1 += v * su1[t * NC + c];
                s2 += v * su2[t * NC + c];
            }
        }
        g_left[g]  = s1 + LR0a;
        g_right[g] = s2 + LR0b;
    }
}

// ---------------- kernel 2: FUSED sort + scans + A-value pack (tables stay in smem) ----------------
__global__ void k_sortaval() {
    __shared__ float ss[2048];
    __shared__ float cumL[2049];
    __shared__ float sufH[2049];
    __shared__ float srb[NN];       // right[] in original order (random access by j)
    __shared__ float wsum[32];
    int b = blockIdx.x;
    int tid = threadIdx.x;
    int lane = tid & 31, warp = tid >> 5;

    {
        float r0 = (tid < NN)        ? g_right[b * NN + tid]        : INFINITY;
        float r1 = (tid + 1024 < NN) ? g_right[b * NN + tid + 1024] : INFINITY;
        ss[tid] = r0;
        ss[tid + 1024] = r1;
        if (tid < NN) srb[tid] = r0;
        if (tid + 1024 < NN) srb[tid + 1024] = r1;
    }
    __syncthreads();

    // bitonic ascending; j<32 stages via shfl
    for (int k2 = 2; k2 <= 2048; k2 <<= 1) {
        for (int j = k2 >> 1; j >= 32; j >>= 1) {
#pragma unroll
            for (int r = 0; r < 2; r++) {
                int e = tid + r * 1024;
                int p = e ^ j;
                if (p > e) {
                    bool up = ((e & k2) == 0);
                    float av = ss[e], bvv = ss[p];
                    if ((av > bvv) == up) { ss[e] = bvv; ss[p] = av; }
                }
            }
            __syncthreads();
        }
        int e0 = tid, e1 = tid + 1024;
        float r0 = ss[e0], r1 = ss[e1];
        bool up0 = ((e0 & k2) == 0);
        bool up1 = ((e1 & k2) == 0);
        int jstart = (k2 >= 32) ? 16 : (k2 >> 1);
        for (int j = jstart; j >= 1; j >>= 1) {
            float p0 = __shfl_xor_sync(0xffffffffu, r0, j);
            float p1 = __shfl_xor_sync(0xffffffffu, r1, j);
            bool lo0 = ((e0 & j) == 0);
            bool lo1 = ((e1 & j) == 0);
            r0 = (lo0 == up0) ? fminf(r0, p0) : fmaxf(r0, p0);
            r1 = (lo1 == up1) ? fminf(r1, p1) : fmaxf(r1, p1);
        }
        ss[e0] = r0; ss[e1] = r1;
        __syncthreads();
    }

    // prefix scan of exp(0.2*sorted) -> cumL (exclusive)
    {
        int e0 = 2 * tid, e1 = 2 * tid + 1;
        float v0 = (e0 < NN) ? expf(0.2f * ss[e0]) : 0.f;
        float v1 = (e1 < NN) ? expf(0.2f * ss[e1]) : 0.f;
        float s = v0 + v1;
        float sc = s;
#pragma unroll
        for (int o = 1; o < 32; o <<= 1) {
            float nn = __shfl_up_sync(0xffffffffu, sc, o);
            if (lane >= o) sc += nn;
        }
        if (lane == 31) wsum[warp] = sc;
        __syncthreads();
        if (tid < 32) {
            float v = wsum[tid];
            float scv = v;
#pragma unroll
            for (int o = 1; o < 32; o <<= 1) {
                float nn = __shfl_up_sync(0xffffffffu, scv, o);
                if (tid >= o) scv += nn;
            }
            wsum[tid] = scv - v;
        }
        __syncthreads();
        float base = wsum[warp] + (sc - s);
        cumL[e0 + 1] = base + v0;
        cumL[e1 + 1] = base + v0 + v1;
        if (tid == 0) cumL[0] = 0.f;
        __syncthreads();
    }

    // suffix scan of exp(sorted) -> sufH
    {
        int e0 = 2047 - 2 * tid;
        int e1 = 2046 - 2 * tid;
        float v0 = (e0 < NN) ? expf(ss[e0]) : 0.f;
        float v1 = (e1 < NN) ? expf(ss[e1]) : 0.f;
        float s = v0 + v1;
        float sc = s;
#pragma unroll
        for (int o = 1; o < 32; o <<= 1) {
            float nn = __shfl_up_sync(0xffffffffu, sc, o);
            if (lane >= o) sc += nn;
        }
        if (lane == 31) wsum[warp] = sc;
        __syncthreads();
        if (tid < 32) {
            float v = wsum[tid];
            float scv = v;
#pragma unroll
            for (int o = 1; o < 32; o <<= 1) {
                float nn = __shfl_up_sync(0xffffffffu, scv, o);
                if (tid >= o) scv += nn;
            }
            wsum[tid] = scv - v;
        }
        __syncthreads();
        float base = wsum[warp] + (sc - s);
        sufH[e0] = base + v0;
        sufH[e1] = base + v0 + v1;
        if (tid == 0) sufH[2048] = 0.f;
        __syncthreads();
    }

    // A values: binary search + pack, all tables in smem
    unsigned* pkb = g_pku + (size_t)b * NK * NN;
#pragma unroll
    for (int r = 0; r < 2; r++) {
        int i = tid + r * 1024;
        if (i >= NN) continue;
        float l = g_left[b * NN + i];
        float theta = -l;
        int lo = 0, hi = 2048;
        while (lo < hi) {
            int mid = (lo + hi) >> 1;
            if (ss[mid] < theta) lo = mid + 1; else hi = mid;
        }
        float denom = expf(l) * sufH[lo] + expf(0.2f * l) * cumL[lo];
        float inv = 1.0f / denom;
#pragma unroll
        for (int k = 0; k < NK; k++) {
            int j = g_idx_t[k * NN + i];          // coalesced
            float a1v = g_adj1v_t[k * NN + i];    // coalesced
            float s = l + srb[j];
            float num = (s >= 0.f) ? expf(s) : expf(0.2f * s);
            float aval = num * inv + a1v;
            unsigned u = ((unsigned)__half_as_ushort(__float2half_rn(aval)) << 16) | (unsigned)j;
            pkb[(size_t)k * NN + i] = u;          // coalesced
        }
    }
}

// ---------------- kernel 3: fused 2-step propagation, fp16 slabs + packed pk ----------------
__device__ __forceinline__ void unpack8(uint4 u, float2& f0, float2& f1, float2& f2, float2& f3) {
    f0 = __half22float2(*reinterpret_cast<__half2*>(&u.x));
    f1 = __half22float2(*reinterpret_cast<__half2*>(&u.y));
    f2 = __half22float2(*reinterpret_cast<__half2*>(&u.z));
    f3 = __half22float2(*reinterpret_cast<__half2*>(&u.w));
}

__global__ void __launch_bounds__(PB, 2) k_prop(const float* __restrict__ x) {
    extern __shared__ uint4 smv[];
    uint4* sx = smv;          // x chunk, fp16x8 per node
    uint4* sh = smv + NN;     // h1 chunk

    int tid = threadIdx.x;
    int chunk = blockIdx.x;
    int bt = blockIdx.y;
    int b = bt / NT, t = bt - b * NT;
    int ch0 = chunk * CH;

    const size_t P = (size_t)NT * NN;
    const float* xs = x + ((size_t)(b * NC + ch0) * NT + t) * NN;
    for (int n = tid; n < NN; n += PB) {
        uint4 u;
        *reinterpret_cast<__half2*>(&u.x) = __float22half2_rn(make_float2(xs[n],       xs[P + n]));
        *reinterpret_cast<__half2*>(&u.y) = __float22half2_rn(make_float2(xs[2*P + n], xs[3*P + n]));
        *reinterpret_cast<__half2*>(&u.z) = __float22half2_rn(make_float2(xs[4*P + n], xs[5*P + n]));
        *reinterpret_cast<__half2*>(&u.w) = __float22half2_rn(make_float2(xs[6*P + n], xs[7*P + n]));
        sx[n] = u;
    }
    __syncthreads();

    const unsigned* pkb = g_pku + (size_t)b * NK * NN;

    // ---- step 1: h1 = 0.05 x + 0.95 A x ----
    for (int m = tid; m < NN; m += PB) {
        float2 a0 = {0.f,0.f}, a1 = {0.f,0.f}, a2 = {0.f,0.f}, a3 = {0.f,0.f};
#pragma unroll
        for (int k = 0; k < NK; k++) {
            unsigned u = pkb[(size_t)k * NN + m];       // coalesced LDG.32
            int j = u & 0xFFFFu;
            float av = __half2float(__ushort_as_half((unsigned short)(u >> 16)));
            float2 f0, f1, f2, f3; unpack8(sx[j], f0, f1, f2, f3);
            a0.x += av*f0.x; a0.y += av*f0.y;
            a1.x += av*f1.x; a1.y += av*f1.y;
            a2.x += av*f2.x; a2.y += av*f2.y;
            a3.x += av*f3.x; a3.y += av*f3.y;
        }
        float2 o0, o1, o2, o3; unpack8(sx[m], o0, o1, o2, o3);
        uint4 u;
        *reinterpret_cast<__half2*>(&u.x) = __float22half2_rn(
            make_float2(0.05f*o0.x + 0.95f*a0.x, 0.05f*o0.y + 0.95f*a0.y));
        *reinterpret_cast<__half2*>(&u.y) = __float22half2_rn(
            make_float2(0.05f*o1.x + 0.95f*a1.x, 0.05f*o1.y + 0.95f*a1.y));
        *reinterpret_cast<__half2*>(&u.z) = __float22half2_rn(
            make_float2(0.05f*o2.x + 0.95f*a2.x, 0.05f*o2.y + 0.95f*a2.y));
        *reinterpret_cast<__half2*>(&u.w) = __float22half2_rn(
            make_float2(0.05f*o3.x + 0.95f*a3.x, 0.05f*o3.y + 0.95f*a3.y));
        sh[m] = u;
    }
    __syncthreads();

    // ---- step 2: h2 = 0.05 x + 0.95 A h1 ; store fp16 planes ----
    __half* h2 = g_h2h + ((size_t)bt * NC + ch0) * NN;
    for (int m = tid; m < NN; m += PB) {
        float2 a0 = {0.f,0.f}, a1 = {0.f,0.f}, a2 = {0.f,0.f}, a3 = {0.f,0.f};
#pragma unroll
        for (int k = 0; k < NK; k++) {
            unsigned u = pkb[(size_t)k * NN + m];
            int j = u & 0xFFFFu;
            float av = __half2float(__ushort_as_half((unsigned short)(u >> 16)));
            float2 f0, f1, f2, f3; unpack8(sh[j], f0, f1, f2, f3);
            a0.x += av*f0.x; a0.y += av*f0.y;
            a1.x += av*f1.x; a1.y += av*f1.y;
            a2.x += av*f2.x; a2.y += av*f2.y;
            a3.x += av*f3.x; a3.y += av*f3.y;
        }
        float2 o0, o1, o2, o3; unpack8(sx[m], o0, o1, o2, o3);
        h2[m]              = __float2half_rn(0.05f*o0.x + 0.95f*a0.x);
        h2[(size_t)NN + m]   = __float2half_rn(0.05f*o0.y + 0.95f*a0.y);
        h2[(size_t)2*NN + m] = __float2half_rn(0.05f*o1.x + 0.95f*a1.x);
        h2[(size_t)3*NN + m] = __float2half_rn(0.05f*o1.y + 0.95f*a1.y);
        h2[(size_t)4*NN + m] = __float2half_rn(0.05f*o2.x + 0.95f*a2.x);
        h2[(size_t)5*NN + m] = __float2half_rn(0.05f*o2.y + 0.95f*a2.y);
        h2[(size_t)6*NN + m] = __float2half_rn(0.05f*o3.x + 0.95f*a3.x);
        h2[(size_t)7*NN + m] = __float2half_rn(0.05f*o3.y + 0.95f*a3.y);
    }
}

// ---------------- kernel 4: output projection, vectorized (2 nodes/thread) ----------------
__global__ void k_out(float* __restrict__ out, const float* __restrict__ W1,
                      const float* __restrict__ b1) {
    __shared__ float W1s[NC * NC];
    __shared__ float b1s[NC];
    int tid = threadIdx.x;
    for (int i = tid; i < NC * NC; i += 128) W1s[i] = W1[i];
    if (tid < NC) b1s[tid] = b1[tid];
    __syncthreads();
    int bt = blockIdx.y;
    int b = bt / NT, t = bt - b * NT;
    int n2 = blockIdx.x * 128 + tid;       // pair index; node pair (2*n2, 2*n2+1)
    if (n2 >= NN / 2) return;
    const __half2* hb = reinterpret_cast<const __half2*>(g_h2h + (size_t)bt * NC * NN);
    float2 h[NC];
#pragma unroll
    for (int cc = 0; cc < NC; cc++)
        h[cc] = __half22float2(hb[(size_t)cc * (NN / 2) + n2]);
#pragma unroll
    for (int o = 0; o < NC; o++) {
        float sA = b1s[o], sB = b1s[o];
#pragma unroll
        for (int cc = 0; cc < NC; cc++) {
            float w = W1s[o * NC + cc];
            sA += w * h[cc].x;
            sB += w * h[cc].y;
        }
        float2* op = reinterpret_cast<float2*>(out + ((size_t)(b * NC + o) * NT + t) * NN);
        op[n2] = make_float2(sA, sB);
    }
}

// ---------------- launch ----------------
extern "C" void kernel_launch(void* const* d_in, const int* in_sizes, int n_in,
                              void* d_out, int out_size) {
    const float* x   = (const float*)d_in[0];
    const float* adj = (const float*)d_in[1];
    const float* W1  = (const float*)d_in[2];
    const float* b1  = (const float*)d_in[3];
    const float* W2  = (const float*)d_in[4];
    const float* b2  = (const float*)d_in[5];
    const float* a   = (const float*)d_in[6];
    float* out = (float*)d_out;

    int prop_smem = 2 * NN * (int)sizeof(uint4);    // 64000 B
    cudaFuncSetAttribute(k_prop, cudaFuncAttributeMaxDynamicSharedMemorySize, prop_smem);
    int adjlr_smem = 4 * NN * (int)sizeof(float);   // 32000 B
    cudaFuncSetAttribute(k_adjlr, cudaFuncAttributeMaxDynamicSharedMemorySize, adjlr_smem);

    k_adjlr<<<ADJ_BLOCKS + LR_BLOCKS, 128, adjlr_smem>>>(adj, x, W2, b2, a);
    k_sortaval<<<NB, 1024>>>();
    {
        dim3 grid(NCHUNK, BT);
        k_prop<<<grid, PB, prop_smem>>>(x);
    }
    {
        dim3 grid((NN / 2 + 127) / 128, BT);
        k_out<<<grid, 128>>>(out, W1, b1);
    }
}

// round 13
// speedup vs baseline: 2.7776x; 1.0088x over previous
#include <cuda_runtime.h>
#include <cuda_fp16.h>
#include <math.h>

#define NB 16
#define NC 32
#define NT 13
#define NN 2000
#define NK 20
#define ND (NT*NC)      // 416
#define BT (NB*NT)      // 208
#define CH 8            // channels per prop chunk (packed as 4 half2 = 16B)
#define NCHUNK (NC/CH)  // 4
#define PB 512          // k_prop block size

#define ADJ_BLOCKS 500  // 4 rows per block
#define LR_BLOCKS  250  // 32000 / 128

// ---------------- scratch (device globals; no allocation allowed) ----------------
__device__ __half   g_h2h[(size_t)BT*NC*NN]; // h after 2 prop steps, fp16, [bt][c][n]
__device__ float    g_left[NB*NN];
__device__ float    g_right[NB*NN];
__device__ int      g_idx_t[NK*NN];          // TRANSPOSED [k][n]
__device__ float    g_adj1v_t[NK*NN];        // TRANSPOSED [k][n]
__device__ unsigned g_pku[(size_t)NB*NK*NN]; // packed {half aval | uint16 idx} at [b][k][n]

// ---------------- kernel 1: FUSED [adj topK (float4 scan, top-2 lanes)] || [u + left/right] ----------------
__global__ void k_adjlr(const float* __restrict__ adj, const float* __restrict__ x,
                        const float* __restrict__ W2, const float* __restrict__ b2,
                        const float* __restrict__ a) {
    extern __shared__ float dsm[];
    if (blockIdx.x < ADJ_BLOCKS) {
        int warp = threadIdx.x >> 5, lane = threadIdx.x & 31;
        int row = blockIdx.x * 4 + warp;
        if (row >= NN) return;
        float* v = dsm + warp * NN;
        const float4* arow4 = reinterpret_cast<const float4*>(adj + (size_t)row * NN);

        float psum = 0.f;
        float bv1 = -1.f, bv2 = -1.f; int bi1 = 0, bi2 = 0;
        bool valid2 = true;
#pragma unroll 4
        for (int q = 0; q < 16; q++) {
            int e4 = lane + 32 * q;
            if (e4 < NN / 4) {
                float4 xv4 = arow4[e4];
                float vv[4] = {xv4.x, xv4.y, xv4.z, xv4.w};
#pragma unroll
                for (int s = 0; s < 4; s++) {
                    float xv = vv[s] > 0.f ? vv[s] : 0.f;
                    int e = 4 * e4 + s;
                    v[e] = xv;
                    psum += xv;
                    if (xv > bv1)      { bv2 = bv1; bi2 = bi1; bv1 = xv; bi1 = e; }
                    else if (xv > bv2) { bv2 = xv; bi2 = e; }
                }
            }
        }
#pragma unroll
        for (int o = 16; o > 0; o >>= 1) psum += __shfl_xor_sync(0xffffffffu, psum, o);
        float invdeg = 1.0f / psum;

        for (int it = 0; it < NK; it++) {
            float mv = bv1; int mi = bi1;
#pragma unroll
            for (int o = 16; o > 0; o >>= 1) {
                float ov = __shfl_xor_sync(0xffffffffu, mv, o);
                int   oi = __shfl_xor_sync(0xffffffffu, mi, o);
                if (ov > mv || (ov == mv && oi < mi)) { mv = ov; mi = oi; }
            }
            if (lane == 0) {
                g_idx_t[it * NN + row]   = mi;
                g_adj1v_t[it * NN + row] = mv * invdeg;
            }
            // owner lane of element e is (e/4) % 32
            if (((mi >> 2) & 31) == lane) {
                v[mi] = -2.0f;
                if (valid2) { bv1 = bv2; bi1 = bi2; valid2 = false; }
                else {
                    bv1 = -1.f; bi1 = 0; bv2 = -1.f; bi2 = 0;
                    const float4* v4 = reinterpret_cast<const float4*>(v);
#pragma unroll 4
                    for (int q = 0; q < 16; q++) {
                        int e4 = lane + 32 * q;
                        if (e4 < NN / 4) {
                            float4 xv4 = v4[e4];
                            float vv[4] = {xv4.x, xv4.y, xv4.z, xv4.w};
#pragma unroll
                            for (int s = 0; s < 4; s++) {
                                float xv = vv[s];
                                int e = 4 * e4 + s;
                                if (xv > bv1)      { bv2 = bv1; bi2 = bi1; bv1 = xv; bi1 = e; }
                                else if (xv > bv2) { bv2 = xv; bi2 = e; }
                            }
                        }
                    }
                    valid2 = true;
                }
            }
            __syncwarp();
        }
    } else {
        float* su1 = dsm;
        float* su2 = dsm + ND;
        float* red = dsm + 2 * ND;     // 8 floats scratch
        int tid = threadIdx.x;
        int lane = tid & 31, warp = tid >> 5;
        // compute u1/u2 inline
        for (int i = tid; i < ND; i += 128) {
            int t = i >> 5, c = i & 31;
            float s1 = 0.f, s2 = 0.f;
            for (int o = 0; o < NC; o++) {
                float w = W2[o * NC + c];
                s1 += a[t * NC + o] * w;
                s2 += a[ND + t * NC + o] * w;
            }
            su1[i] = s1; su2[i] = s2;
        }
        // LR0 constants
        float p1 = 0.f, p2 = 0.f;
        for (int d = tid; d < ND; d += 128) {
            float bb = b2[d & 31];
            p1 += bb * a[d];
            p2 += bb * a[ND + d];
        }
#pragma unroll
        for (int o = 16; o > 0; o >>= 1) {
            p1 += __shfl_xor_sync(0xffffffffu, p1, o);
            p2 += __shfl_xor_sync(0xffffffffu, p2, o);
        }
        if (lane == 0) { red[warp] = p1; red[4 + warp] = p2; }
        __syncthreads();
        float LR0a = red[0] + red[1] + red[2] + red[3];
        float LR0b = red[4] + red[5] + red[6] + red[7];

        int g = (blockIdx.x - ADJ_BLOCKS) * 128 + tid;   // 0..31999
        int b = g / NN, n = g - b * NN;
        const float* xb = x + (size_t)b * NC * NT * NN + n;
        float s1 = 0.f, s2 = 0.f;
#pragma unroll 4
        for (int c = 0; c < NC; c++) {
#pragma unroll
            for (int t = 0; t < NT; t++) {
                float v = xb[(size_t)(c * NT + t) * NN];
                s1 += v * su1[t * NC + c];
                s2 += v * su2[t * NC + c];
            }
        }
        g_left[g]  = s1 + LR0a;
        g_right[g] = s2 + LR0b;
    }
}

// ---------------- kernel 2: FUSED sort + scans + A-value pack (tables stay in smem) ----------------
__global__ void k_sortaval() {
    __shared__ float ss[2048];
    __shared__ float cumL[2049];
    __shared__ float sufH[2049];
    __shared__ float srb[NN];       // right[] in original order (random access by j)
    __shared__ float wsum[32];
    int b = blockIdx.x;
    int tid = threadIdx.x;
    int lane = tid & 31, warp = tid >> 5;

    {
        float r0 = (tid < NN)        ? g_right[b * NN + tid]        : INFINITY;
        float r1 = (tid + 1024 < NN) ? g_right[b * NN + tid + 1024] : INFINITY;
        ss[tid] = r0;
        ss[tid + 1024] = r1;
        if (tid < NN) srb[tid] = r0;
        if (tid + 1024 < NN) srb[tid + 1024] = r1;
    }
    __syncthreads();

    // bitonic ascending; j<32 stages via shfl
    for (int k2 = 2; k2 <= 2048; k2 <<= 1) {
        for (int j = k2 >> 1; j >= 32; j >>= 1) {
#pragma unroll
            for (int r = 0; r < 2; r++) {
                int e = tid + r * 1024;
                int p = e ^ j;
                if (p > e) {
                    bool up = ((e & k2) == 0);
                    float av = ss[e], bvv = ss[p];
                    if ((av > bvv) == up) { ss[e] = bvv; ss[p] = av; }
                }
            }
            __syncthreads();
        }
        int e0 = tid, e1 = tid + 1024;
        float r0 = ss[e0], r1 = ss[e1];
        bool up0 = ((e0 & k2) == 0);
        bool up1 = ((e1 & k2) == 0);
        int jstart = (k2 >= 32) ? 16 : (k2 >> 1);
        for (int j = jstart; j >= 1; j >>= 1) {
            float p0 = __shfl_xor_sync(0xffffffffu, r0, j);
            float p1 = __shfl_xor_sync(0xffffffffu, r1, j);
            bool lo0 = ((e0 & j) == 0);
            bool lo1 = ((e1 & j) == 0);
            r0 = (lo0 == up0) ? fminf(r0, p0) : fmaxf(r0, p0);
            r1 = (lo1 == up1) ? fminf(r1, p1) : fmaxf(r1, p1);
        }
        ss[e0] = r0; ss[e1] = r1;
        __syncthreads();
    }

    // prefix scan of exp(0.2*sorted) -> cumL (exclusive)
    {
        int e0 = 2 * tid, e1 = 2 * tid + 1;
        float v0 = (e0 < NN) ? expf(0.2f * ss[e0]) : 0.f;
        float v1 = (e1 < NN) ? expf(0.2f * ss[e1]) : 0.f;
        float s = v0 + v1;
        float sc = s;
#pragma unroll
        for (int o = 1; o < 32; o <<= 1) {
            float nn = __shfl_up_sync(0xffffffffu, sc, o);
            if (lane >= o) sc += nn;
        }
        if (lane == 31) wsum[warp] = sc;
        __syncthreads();
        if (tid < 32) {
            float v = wsum[tid];
            float scv = v;
#pragma unroll
            for (int o = 1; o < 32; o <<= 1) {
                float nn = __shfl_up_sync(0xffffffffu, scv, o);
                if (tid >= o) scv += nn;
            }
            wsum[tid] = scv - v;
        }
        __syncthreads();
        float base = wsum[warp] + (sc - s);
        cumL[e0 + 1] = base + v0;
        cumL[e1 + 1] = base + v0 + v1;
        if (tid == 0) cumL[0] = 0.f;
        __syncthreads();
    }

    // suffix scan of exp(sorted) -> sufH
    {
        int e0 = 2047 - 2 * tid;
        int e1 = 2046 - 2 * tid;
        float v0 = (e0 < NN) ? expf(ss[e0]) : 0.f;
        float v1 = (e1 < NN) ? expf(ss[e1]) : 0.f;
        float s = v0 + v1;
        float sc = s;
#pragma unroll
        for (int o = 1; o < 32; o <<= 1) {
            float nn = __shfl_up_sync(0xffffffffu, sc, o);
            if (lane >= o) sc += nn;
        }
        if (lane == 31) wsum[warp] = sc;
        __syncthreads();
        if (tid < 32) {
            float v = wsum[tid];
            float scv = v;
#pragma unroll
            for (int o = 1; o < 32; o <<= 1) {
                float nn = __shfl_up_sync(0xffffffffu, scv, o);
                if (tid >= o) scv += nn;
            }
            wsum[tid] = scv - v;
        }
        __syncthreads();
        float base = wsum[warp] + (sc - s);
        sufH[e0] = base + v0;
        sufH[e1] = base + v0 + v1;
        if (tid == 0) sufH[2048] = 0.f;
        __syncthreads();
    }

    // A values: binary search + pack, all tables in smem
    unsigned* pkb = g_pku + (size_t)b * NK * NN;
#pragma unroll
    for (int r = 0; r < 2; r++) {
        int i = tid + r * 1024;
        if (i >= NN) continue;
        float l = g_left[b * NN + i];
        float theta = -l;
        int lo = 0, hi = 2048;
        while (lo < hi) {
            int mid = (lo + hi) >> 1;
            if (ss[mid] < theta) lo = mid + 1; else hi = mid;
        }
        float denom = expf(l) * sufH[lo] + expf(0.2f * l) * cumL[lo];
        float inv = 1.0f / denom;
#pragma unroll
        for (int k = 0; k < NK; k++) {
            int j = g_idx_t[k * NN + i];          // coalesced
            float a1v = g_adj1v_t[k * NN + i];    // coalesced
            float s = l + srb[j];
            float num = (s >= 0.f) ? expf(s) : expf(0.2f * s);
            float aval = num * inv + a1v;
            unsigned u = ((unsigned)__half_as_ushort(__float2half_rn(aval)) << 16) | (unsigned)j;
            pkb[(size_t)k * NN + i] = u;          // coalesced
        }
    }
}

// ---------------- kernel 3: fused 2-step propagation, fp16 slabs + packed pk ----------------
__device__ __forceinline__ void unpack8(uint4 u, float2& f0, float2& f1, float2& f2, float2& f3) {
    f0 = __half22float2(*reinterpret_cast<__half2*>(&u.x));
    f1 = __half22float2(*reinterpret_cast<__half2*>(&u.y));
    f2 = __half22float2(*reinterpret_cast<__half2*>(&u.z));
    f3 = __half22float2(*reinterpret_cast<__half2*>(&u.w));
}

__global__ void __launch_bounds__(PB, 2) k_prop(const float* __restrict__ x) {
    extern __shared__ uint4 smv[];
    uint4* sx = smv;          // x chunk, fp16x8 per node
    uint4* sh = smv + NN;     // h1 chunk

    int tid = threadIdx.x;
    int chunk = blockIdx.x;
    int bt = blockIdx.y;
    int b = bt / NT, t = bt - b * NT;
    int ch0 = chunk * CH;

    const size_t P = (size_t)NT * NN;
    const float* xs = x + ((size_t)(b * NC + ch0) * NT + t) * NN;
    for (int n = tid; n < NN; n += PB) {
        uint4 u;
        *reinterpret_cast<__half2*>(&u.x) = __float22half2_rn(make_float2(xs[n],       xs[P + n]));
        *reinterpret_cast<__half2*>(&u.y) = __float22half2_rn(make_float2(xs[2*P + n], xs[3*P + n]));
        *reinterpret_cast<__half2*>(&u.z) = __float22half2_rn(make_float2(xs[4*P + n], xs[5*P + n]));
        *reinterpret_cast<__half2*>(&u.w) = __float22half2_rn(make_float2(xs[6*P + n], xs[7*P + n]));
        sx[n] = u;
    }
    __syncthreads();

    const unsigned* pkb = g_pku + (size_t)b * NK * NN;

    // ---- step 1: h1 = 0.05 x + 0.95 A x ----
    for (int m = tid; m < NN; m += PB) {
        float2 a0 = {0.f,0.f}, a1 = {0.f,0.f}, a2 = {0.f,0.f}, a3 = {0.f,0.f};
#pragma unroll
        for (int k = 0; k < NK; k++) {
            unsigned u = pkb[(size_t)k * NN + m];       // coalesced LDG.32
            int j = u & 0xFFFFu;
            float av = __half2float(__ushort_as_half((unsigned short)(u >> 16)));
            float2 f0, f1, f2, f3; unpack8(sx[j], f0, f1, f2, f3);
            a0.x += av*f0.x; a0.y += av*f0.y;
            a1.x += av*f1.x; a1.y += av*f1.y;
            a2.x += av*f2.x; a2.y += av*f2.y;
            a3.x += av*f3.x; a3.y += av*f3.y;
        }
        float2 o0, o1, o2, o3; unpack8(sx[m], o0, o1, o2, o3);
        uint4 u;
        *reinterpret_cast<__half2*>(&u.x) = __float22half2_rn(
            make_float2(0.05f*o0.x + 0.95f*a0.x, 0.05f*o0.y + 0.95f*a0.y));
        *reinterpret_cast<__half2*>(&u.y) = __float22half2_rn(
            make_float2(0.05f*o1.x + 0.95f*a1.x, 0.05f*o1.y + 0.95f*a1.y));
        *reinterpret_cast<__half2*>(&u.z) = __float22half2_rn(
            make_float2(0.05f*o2.x + 0.95f*a2.x, 0.05f*o2.y + 0.95f*a2.y));
        *reinterpret_cast<__half2*>(&u.w) = __float22half2_rn(
            make_float2(0.05f*o3.x + 0.95f*a3.x, 0.05f*o3.y + 0.95f*a3.y));
        sh[m] = u;
    }
    __syncthreads();

    // ---- step 2: h2 = 0.05 x + 0.95 A h1 ; store fp16 planes ----
    __half* h2 = g_h2h + ((size_t)bt * NC + ch0) * NN;
    for (int m = tid; m < NN; m += PB) {
        float2 a0 = {0.f,0.f}, a1 = {0.f,0.f}, a2 = {0.f,0.f}, a3 = {0.f,0.f};
#pragma unroll
        for (int k = 0; k < NK; k++) {
            unsigned u = pkb[(size_t)k * NN + m];
            int j = u & 0xFFFFu;
            float av = __half2float(__ushort_as_half((unsigned short)(u >> 16)));
            float2 f0, f1, f2, f3; unpack8(sh[j], f0, f1, f2, f3);
            a0.x += av*f0.x; a0.y += av*f0.y;
            a1.x += av*f1.x; a1.y += av*f1.y;
            a2.x += av*f2.x; a2.y += av*f2.y;
            a3.x += av*f3.x; a3.y += av*f3.y;
        }
        float2 o0, o1, o2, o3; unpack8(sx[m], o0, o1, o2, o3);
        h2[m]              = __float2half_rn(0.05f*o0.x + 0.95f*a0.x);
        h2[(size_t)NN + m]   = __float2half_rn(0.05f*o0.y + 0.95f*a0.y);
        h2[(size_t)2*NN + m] = __float2half_rn(0.05f*o1.x + 0.95f*a1.x);
        h2[(size_t)3*NN + m] = __float2half_rn(0.05f*o1.y + 0.95f*a1.y);
        h2[(size_t)4*NN + m] = __float2half_rn(0.05f*o2.x + 0.95f*a2.x);
        h2[(size_t)5*NN + m] = __float2half_rn(0.05f*o2.y + 0.95f*a2.y);
        h2[(size_t)6*NN + m] = __float2half_rn(0.05f*o3.x + 0.95f*a3.x);
        h2[(size_t)7*NN + m] = __float2half_rn(0.05f*o3.y + 0.95f*a3.y);
    }
}

// ---------------- kernel 4: output projection via HMMA (m16n8k16) ----------------
#define MMA16816(d0,d1,d2,d3,a0,a1,a2,a3,b0,b1) \
    asm volatile("mma.sync.aligned.m16n8k16.row.col.f32.f16.f16.f32 " \
        "{%0,%1,%2,%3}, {%4,%5,%6,%7}, {%8,%9}, {%0,%1,%2,%3};" \
        : "+f"(d0), "+f"(d1), "+f"(d2), "+f"(d3) \
        : "r"(a0), "r"(a1), "r"(a2), "r"(a3), "r"(b0), "r"(b1))

#define WPITCH 34   // padded half pitch

__global__ void __launch_bounds__(256) k_out(float* __restrict__ out,
                                             const float* __restrict__ W1,
                                             const float* __restrict__ b1) {
    __shared__ __half sW[NC * WPITCH];        // W1 fp16, [o][c] padded
    __shared__ __half hB[256 * WPITCH];       // h2 tile transposed, [n][c] padded
    __shared__ float  b1s[NC];
    int tid = threadIdx.x, lane = tid & 31, warp = tid >> 5;
    int bt = blockIdx.y;
    int b = bt / NT, t = bt - b * NT;
    int n0 = blockIdx.x * 256;

    for (int i = tid; i < NC * NC; i += 256) {
        int o = i >> 5, c = i & 31;
        sW[o * WPITCH + c] = __float2half_rn(W1[i]);
    }
    if (tid < NC) b1s[tid] = b1[tid];

    // stage h2 tile transposed: hB[n][c]
    const __half* hplane = g_h2h + (size_t)bt * NC * NN;
#pragma unroll
    for (int p = 0; p < 4; p++) {
        int c = warp + 8 * p;
        int nst = lane * 8;
        __half hv[8];
        if (n0 + nst + 8 <= NN) {
            uint4 u = *reinterpret_cast<const uint4*>(hplane + (size_t)c * NN + n0 + nst);
            const __half* up = reinterpret_cast<const __half*>(&u);
#pragma unroll
            for (int s = 0; s < 8; s++) hv[s] = up[s];
        } else {
#pragma unroll
            for (int s = 0; s < 8; s++) hv[s] = __ushort_as_half(0);
        }
#pragma unroll
        for (int s = 0; s < 8; s++) hB[(nst + s) * WPITCH + c] = hv[s];
    }
    __syncthreads();

    int g = lane >> 2, t4 = lane & 3;

    // A fragments: [m tile][k step][4 regs]
    unsigned afr[2][2][4];
#pragma unroll
    for (int m = 0; m < 2; m++) {
#pragma unroll
        for (int k = 0; k < 2; k++) {
            const __half* base = sW + (m * 16 + g) * WPITCH + k * 16 + 2 * t4;
            afr[m][k][0] = *reinterpret_cast<const unsigned*>(base);                    // A[g][2t]
            afr[m][k][1] = *reinterpret_cast<const unsigned*>(base + 8 * WPITCH);       // A[g+8][2t]
            afr[m][k][2] = *reinterpret_cast<const unsigned*>(base + 8);                // A[g][2t+8]
            afr[m][k][3] = *reinterpret_cast<const unsigned*>(base + 8 * WPITCH + 8);   // A[g+8][2t+8]
        }
    }

#pragma unroll
    for (int s = 0; s < 4; s++) {
        int nl = warp * 32 + s * 8;
        // B fragments for both k steps: b0 = {B[2t][g], B[2t+1][g]}, b1 = rows +8
        unsigned bfr[2][2];
#pragma unroll
        for (int k = 0; k < 2; k++) {
            const __half* base = hB + (nl + g) * WPITCH + k * 16 + 2 * t4;
            bfr[k][0] = *reinterpret_cast<const unsigned*>(base);
            bfr[k][1] = *reinterpret_cast<const unsigned*>(base + 8);
        }
#pragma unroll
        for (int m = 0; m < 2; m++) {
            float bv0 = b1s[m * 16 + g];
            float bv1 = b1s[m * 16 + g + 8];
            float d0 = bv0, d1 = bv0, d2 = bv1, d3 = bv1;
            MMA16816(d0, d1, d2, d3,
                     afr[m][0][0], afr[m][0][1], afr[m][0][2], afr[m][0][3],
                     bfr[0][0], bfr[0][1]);
            MMA16816(d0, d1, d2, d3,
                     afr[m][1][0], afr[m][1][1], afr[m][1][2], afr[m][1][3],
                     bfr[1][0], bfr[1][1]);
            int o = m * 16 + g;
            int n = n0 + nl + 2 * t4;
            if (n < NN) {
                float* op0 = out + ((size_t)(b * NC + o) * NT + t) * NN;
                float* op1 = out + ((size_t)(b * NC + o + 8) * NT + t) * NN;
                *reinterpret_cast<float2*>(op0 + n) = make_float2(d0, d1);
                *reinterpret_cast<float2*>(op1 + n) = make_float2(d2, d3);
            }
        }
    }
}

// ---------------- launch ----------------
extern "C" void kernel_launch(void* const* d_in, const int* in_sizes, int n_in,
                              void* d_out, int out_size) {
    const float* x   = (const float*)d_in[0];
    const float* adj = (const float*)d_in[1];
    const float* W1  = (const float*)d_in[2];
    const float* b1  = (const float*)d_in[3];
    const float* W2  = (const float*)d_in[4];
    const float* b2  = (const float*)d_in[5];
    const float* a   = (const float*)d_in[6];
    float* out = (float*)d_out;

    int prop_smem = 2 * NN * (int)sizeof(uint4);    // 64000 B
    cudaFuncSetAttribute(k_prop, cudaFuncAttributeMaxDynamicSharedMemorySize, prop_smem);
    int adjlr_smem = 4 * NN * (int)sizeof(float);   // 32000 B
    cudaFuncSetAttribute(k_adjlr, cudaFuncAttributeMaxDynamicSharedMemorySize, adjlr_smem);

    k_adjlr<<<ADJ_BLOCKS + LR_BLOCKS, 128, adjlr_smem>>>(adj, x, W2, b2, a);
    k_sortaval<<<NB, 1024>>>();
    {
        dim3 grid(NCHUNK, BT);
        k_prop<<<grid, PB, prop_smem>>>(x);
    }
    {
        dim3 grid((NN + 255) / 256, BT);
        k_out<<<grid, 256>>>(out, W1, b1);
    }
}

// round 17
// speedup vs baseline: 2.8999x; 1.0440x over previous
#include <cuda_runtime.h>
#include <cuda_fp16.h>
#include <math.h>

#define NB 16
#define NC 32
#define NT 13
#define NN 2000
#define NK 20
#define ND (NT*NC)      // 416
#define BT (NB*NT)      // 208
#define CH 8            // channels per prop chunk (packed as 4 half2 = 16B)
#define NCHUNK (NC/CH)  // 4
#define PB 512          // k_prop block size

#define ADJ_BLOCKS 500  // 4 rows per block
#define LR_BLOCKS  250  // 32000 / 128

// ---------------- scratch (device globals; no allocation allowed) ----------------
__device__ __half   g_h2h[(size_t)BT*NC*NN]; // h after 2 prop steps, fp16, [bt][c][n]
__device__ float    g_left[NB*NN];
__device__ float    g_right[NB*NN];
__device__ int      g_idx_t[NK*NN];          // TRANSPOSED [k][n]
__device__ float    g_adj1v_t[NK*NN];        // TRANSPOSED [k][n]
__device__ unsigned g_pku[(size_t)NB*NK*NN]; // packed {half aval | uint16 idx} at [b][k][n]

// ---------------- kernel 1: FUSED [adj topK (float4 scan, top-2 lanes)] || [u + left/right] ----------------
__global__ void k_adjlr(const float* __restrict__ adj, const float* __restrict__ x,
                        const float* __restrict__ W2, const float* __restrict__ b2,
                        const float* __restrict__ a) {
    extern __shared__ float dsm[];
    if (blockIdx.x < ADJ_BLOCKS) {
        int warp = threadIdx.x >> 5, lane = threadIdx.x & 31;
        int row = blockIdx.x * 4 + warp;
        if (row >= NN) return;
        float* v = dsm + warp * NN;
        const float4* arow4 = reinterpret_cast<const float4*>(adj + (size_t)row * NN);

        float psum = 0.f;
        float bv1 = -1.f, bv2 = -1.f; int bi1 = 0, bi2 = 0;
        bool valid2 = true;
#pragma unroll 4
        for (int q = 0; q < 16; q++) {
            int e4 = lane + 32 * q;
            if (e4 < NN / 4) {
                float4 xv4 = arow4[e4];
                float vv[4] = {xv4.x, xv4.y, xv4.z, xv4.w};
#pragma unroll
                for (int s = 0; s < 4; s++) {
                    float xv = vv[s] > 0.f ? vv[s] : 0.f;
                    int e = 4 * e4 + s;
                    v[e] = xv;
                    psum += xv;
                    if (xv > bv1)      { bv2 = bv1; bi2 = bi1; bv1 = xv; bi1 = e; }
                    else if (xv > bv2) { bv2 = xv; bi2 = e; }
                }
            }
        }
#pragma unroll
        for (int o = 16; o > 0; o >>= 1) psum += __shfl_xor_sync(0xffffffffu, psum, o);
        float invdeg = 1.0f / psum;

        for (int it = 0; it < NK; it++) {
            float mv = bv1; int mi = bi1;
#pragma unroll
            for (int o = 16; o > 0; o >>= 1) {
                float ov = __shfl_xor_sync(0xffffffffu, mv, o);
                int   oi = __shfl_xor_sync(0xffffffffu, mi, o);
                if (ov > mv || (ov == mv && oi < mi)) { mv = ov; mi = oi; }
            }
            if (lane == 0) {
                g_idx_t[it * NN + row]   = mi;
                g_adj1v_t[it * NN + row] = mv * invdeg;
            }
            // owner lane of element e is (e/4) % 32
            if (((mi >> 2) & 31) == lane) {
                v[mi] = -2.0f;
                if (valid2) { bv1 = bv2; bi1 = bi2; valid2 = false; }
                else {
                    bv1 = -1.f; bi1 = 0; bv2 = -1.f; bi2 = 0;
                    const float4* v4 = reinterpret_cast<const float4*>(v);
#pragma unroll 4
                    for (int q = 0; q < 16; q++) {
                        int e4 = lane + 32 * q;
                        if (e4 < NN / 4) {
                            float4 xv4 = v4[e4];
                            float vv[4] = {xv4.x, xv4.y, xv4.z, xv4.w};
#pragma unroll
                            for (int s = 0; s < 4; s++) {
                                float xv = vv[s];
                                int e = 4 * e4 + s;
                                if (xv > bv1)      { bv2 = bv1; bi2 = bi1; bv1 = xv; bi1 = e; }
                                else if (xv > bv2) { bv2 = xv; bi2 = e; }
                            }
                        }
                    }
                    valid2 = true;
                }
            }
            __syncwarp();
        }
    } else {
        float* su1 = dsm;
        float* su2 = dsm + ND;
        float* red = dsm + 2 * ND;     // 8 floats scratch
        int tid = threadIdx.x;
        int lane = tid & 31, warp = tid >> 5;
        // compute u1/u2 inline
        for (int i = tid; i < ND; i += 128) {
            int t = i >> 5, c = i & 31;
            float s1 = 0.f, s2 = 0.f;
            for (int o = 0; o < NC; o++) {
                float w = W2[o * NC + c];
                s1 += a[t * NC + o] * w;
                s2 += a[ND + t * NC + o] * w;
            }
            su1[i] = s1; su2[i] = s2;
        }
        // LR0 constants
        float p1 = 0.f, p2 = 0.f;
        for (int d = tid; d < ND; d += 128) {
            float bb = b2[d & 31];
            p1 += bb * a[d];
            p2 += bb * a[ND + d];
        }
#pragma unroll
        for (int o = 16; o > 0; o >>= 1) {
            p1 += __shfl_xor_sync(0xffffffffu, p1, o);
            p2 += __shfl_xor_sync(0xffffffffu, p2, o);
        }
        if (lane == 0) { red[warp] = p1; red[4 + warp] = p2; }
        __syncthreads();
        float LR0a = red[0] + red[1] + red[2] + red[3];
        float LR0b = red[4] + red[5] + red[6] + red[7];

        int g = (blockIdx.x - ADJ_BLOCKS) * 128 + tid;   // 0..31999
        int b = g / NN, n = g - b * NN;
        const float* xb = x + (size_t)b * NC * NT * NN + n;
        float s1 = 0.f, s2 = 0.f;
#pragma unroll 4
        for (int c = 0; c < NC; c++) {
#pragma unroll
            for (int t = 0; t < NT; t++) {
                float v = xb[(size_t)(c * NT + t) * NN];
                s1 += v * su1[t * NC + c];
                s2 += v * su2[t * NC + c];
            }
        }
        g_left[g]  = s1 + LR0a;
        g_right[g] = s2 + LR0b;
    }
}

// ---------------- kernel 2: FUSED sort + scans + A-value pack (tables stay in smem) ----------------
__global__ void k_sortaval() {
    __shared__ float ss[2048];
    __shared__ float cumL[2049];
    __shared__ float sufH[2049];
    __shared__ float srb[NN];       // right[] in original order (random access by j)
    __shared__ float wsum[32];
    int b = blockIdx.x;
    int tid = threadIdx.x;
    int lane = tid & 31, warp = tid >> 5;

    {
        float r0 = (tid < NN)        ? g_right[b * NN + tid]        : INFINITY;
        float r1 = (tid + 1024 < NN) ? g_right[b * NN + tid + 1024] : INFINITY;
        ss[tid] = r0;
        ss[tid + 1024] = r1;
        if (tid < NN) srb[tid] = r0;
        if (tid + 1024 < NN) srb[tid + 1024] = r1;
    }
    __syncthreads();

    // bitonic ascending; j<32 stages via shfl
    for (int k2 = 2; k2 <= 2048; k2 <<= 1) {
        for (int j = k2 >> 1; j >= 32; j >>= 1) {
#pragma unroll
            for (int r = 0; r < 2; r++) {
                int e = tid + r * 1024;
                int p = e ^ j;
                if (p > e) {
                    bool up = ((e & k2) == 0);
                    float av = ss[e], bvv = ss[p];
                    if ((av > bvv) == up) { ss[e] = bvv; ss[p] = av; }
                }
            }
            __syncthreads();
        }
        int e0 = tid, e1 = tid + 1024;
        float r0 = ss[e0], r1 = ss[e1];
        bool up0 = ((e0 & k2) == 0);
        bool up1 = ((e1 & k2) == 0);
        int jstart = (k2 >= 32) ? 16 : (k2 >> 1);
        for (int j = jstart; j >= 1; j >>= 1) {
            float p0 = __shfl_xor_sync(0xffffffffu, r0, j);
            float p1 = __shfl_xor_sync(0xffffffffu, r1, j);
            bool lo0 = ((e0 & j) == 0);
            bool lo1 = ((e1 & j) == 0);
            r0 = (lo0 == up0) ? fminf(r0, p0) : fmaxf(r0, p0);
            r1 = (lo1 == up1) ? fminf(r1, p1) : fmaxf(r1, p1);
        }
        ss[e0] = r0; ss[e1] = r1;
        __syncthreads();
    }

    // prefix scan of exp(0.2*sorted) -> cumL (exclusive)
    {
        int e0 = 2 * tid, e1 = 2 * tid + 1;
        float v0 = (e0 < NN) ? expf(0.2f * ss[e0]) : 0.f;
        float v1 = (e1 < NN) ? expf(0.2f * ss[e1]) : 0.f;
        float s = v0 + v1;
        float sc = s;
#pragma unroll
        for (int o = 1; o < 32; o <<= 1) {
            float nn = __shfl_up_sync(0xffffffffu, sc, o);
            if (lane >= o) sc += nn;
        }
        if (lane == 31) wsum[warp] = sc;
        __syncthreads();
        if (tid < 32) {
            float v = wsum[tid];
            float scv = v;
#pragma unroll
            for (int o = 1; o < 32; o <<= 1) {
                float nn = __shfl_up_sync(0xffffffffu, scv, o);
                if (tid >= o) scv += nn;
            }
            wsum[tid] = scv - v;
        }
        __syncthreads();
        float base = wsum[warp] + (sc - s);
        cumL[e0 + 1] = base + v0;
        cumL[e1 + 1] = base + v0 + v1;
        if (tid == 0) cumL[0] = 0.f;
        __syncthreads();
    }

    // suffix scan of exp(sorted) -> sufH
    {
        int e0 = 2047 - 2 * tid;
        int e1 = 2046 - 2 * tid;
        float v0 = (e0 < NN) ? expf(ss[e0]) : 0.f;
        float v1 = (e1 < NN) ? expf(ss[e1]) : 0.f;
        float s = v0 + v1;
        float sc = s;
#pragma unroll
        for (int o = 1; o < 32; o <<= 1) {
            float nn = __shfl_up_sync(0xffffffffu, sc, o);
            if (lane >= o) sc += nn;
        }
        if (lane == 31) wsum[warp] = sc;
        __syncthreads();
        if (tid < 32) {
            float v = wsum[tid];
            float scv = v;
#pragma unroll
            for (int o = 1; o < 32; o <<= 1) {
                float nn = __shfl_up_sync(0xffffffffu, scv, o);
                if (tid >= o) scv += nn;
            }
            wsum[tid] = scv - v;
        }
        __syncthreads();
        float base = wsum[warp] + (sc - s);
        sufH[e0] = base + v0;
        sufH[e1] = base + v0 + v1;
        if (tid == 0) sufH[2048] = 0.f;
        __syncthreads();
    }

    // A values: binary search + pack, all tables in smem
    unsigned* pkb = g_pku + (size_t)b * NK * NN;
#pragma unroll
    for (int r = 0; r < 2; r++) {
        int i = tid + r * 1024;
        if (i >= NN) continue;
        float l = g_left[b * NN + i];
        float theta = -l;
        int lo = 0, hi = 2048;
        while (lo < hi) {
            int mid = (lo + hi) >> 1;
            if (ss[mid] < theta) lo = mid + 1; else hi = mid;
        }
        float denom = expf(l) * sufH[lo] + expf(0.2f * l) * cumL[lo];
        float inv = 1.0f / denom;
#pragma unroll
        for (int k = 0; k < NK; k++) {
            int j = g_idx_t[k * NN + i];          // coalesced
            float a1v = g_adj1v_t[k * NN + i];    // coalesced
            float s = l + srb[j];
            float num = (s >= 0.f) ? expf(s) : expf(0.2f * s);
            float aval = num * inv + a1v;
            unsigned u = ((unsigned)__half_as_ushort(__float2half_rn(aval)) << 16) | (unsigned)j;
            pkb[(size_t)k * NN + i] = u;          // coalesced
        }
    }
}

// ---------------- kernel 3: fused 2-step propagation, fp16 slabs + packed pk ----------------
__device__ __forceinline__ void unpack8(uint4 u, float2& f0, float2& f1, float2& f2, float2& f3) {
    f0 = __half22float2(*reinterpret_cast<__half2*>(&u.x));
    f1 = __half22float2(*reinterpret_cast<__half2*>(&u.y));
    f2 = __half22float2(*reinterpret_cast<__half2*>(&u.z));
    f3 = __half22float2(*reinterpret_cast<__half2*>(&u.w));
}

__global__ void __launch_bounds__(PB, 2) k_prop(const float* __restrict__ x) {
    extern __shared__ uint4 smv[];
    uint4* sx = smv;          // x chunk, fp16x8 per node
    uint4* sh = smv + NN;     // h1 chunk

    int tid = threadIdx.x;
    int chunk = blockIdx.x;
    int bt = blockIdx.y;
    int b = bt / NT, t = bt - b * NT;
    int ch0 = chunk * CH;

    const size_t P = (size_t)NT * NN;
    const float* xs = x + ((size_t)(b * NC + ch0) * NT + t) * NN;
    for (int n = tid; n < NN; n += PB) {
        uint4 u;
        *reinterpret_cast<__half2*>(&u.x) = __float22half2_rn(make_float2(xs[n],       xs[P + n]));
        *reinterpret_cast<__half2*>(&u.y) = __float22half2_rn(make_float2(xs[2*P + n], xs[3*P + n]));
        *reinterpret_cast<__half2*>(&u.z) = __float22half2_rn(make_float2(xs[4*P + n], xs[5*P + n]));
        *reinterpret_cast<__half2*>(&u.w) = __float22half2_rn(make_float2(xs[6*P + n], xs[7*P + n]));
        sx[n] = u;
    }
    __syncthreads();

    const unsigned* pkb = g_pku + (size_t)b * NK * NN;

    // ---- step 1: h1 = 0.05 x + 0.95 A x ----
    for (int m = tid; m < NN; m += PB) {
        float2 a0 = {0.f,0.f}, a1 = {0.f,0.f}, a2 = {0.f,0.f}, a3 = {0.f,0.f};
#pragma unroll
        for (int k = 0; k < NK; k++) {
            unsigned u = pkb[(size_t)k * NN + m];       // coalesced LDG.32
            int j = u & 0xFFFFu;
            float av = __half2float(__ushort_as_half((unsigned short)(u >> 16)));
            float2 f0, f1, f2, f3; unpack8(sx[j], f0, f1, f2, f3);
            a0.x += av*f0.x; a0.y += av*f0.y;
            a1.x += av*f1.x; a1.y += av*f1.y;
            a2.x += av*f2.x; a2.y += av*f2.y;
            a3.x += av*f3.x; a3.y += av*f3.y;
        }
        float2 o0, o1, o2, o3; unpack8(sx[m], o0, o1, o2, o3);
        uint4 u;
        *reinterpret_cast<__half2*>(&u.x) = __float22half2_rn(
            make_float2(0.05f*o0.x + 0.95f*a0.x, 0.05f*o0.y + 0.95f*a0.y));
        *reinterpret_cast<__half2*>(&u.y) = __float22half2_rn(
            make_float2(0.05f*o1.x + 0.95f*a1.x, 0.05f*o1.y + 0.95f*a1.y));
        *reinterpret_cast<__half2*>(&u.z) = __float22half2_rn(
            make_float2(0.05f*o2.x + 0.95f*a2.x, 0.05f*o2.y + 0.95f*a2.y));
        *reinterpret_cast<__half2*>(&u.w) = __float22half2_rn(
            make_float2(0.05f*o3.x + 0.95f*a3.x, 0.05f*o3.y + 0.95f*a3.y));
        sh[m] = u;
    }
    __syncthreads();

    // ---- step 2: h2 = 0.05 x + 0.95 A h1 ; store fp16 planes ----
    __half* h2 = g_h2h + ((size_t)bt * NC + ch0) * NN;
    for (int m = tid; m < NN; m += PB) {
        float2 a0 = {0.f,0.f}, a1 = {0.f,0.f}, a2 = {0.f,0.f}, a3 = {0.f,0.f};
#pragma unroll
        for (int k = 0; k < NK; k++) {
            unsigned u = pkb[(size_t)k * NN + m];
            int j = u & 0xFFFFu;
            float av = __half2float(__ushort_as_half((unsigned short)(u >> 16)));
            float2 f0, f1, f2, f3; unpack8(sh[j], f0, f1, f2, f3);
            a0.x += av*f0.x; a0.y += av*f0.y;
            a1.x += av*f1.x; a1.y += av*f1.y;
            a2.x += av*f2.x; a2.y += av*f2.y;
            a3.x += av*f3.x; a3.y += av*f3.y;
        }
        float2 o0, o1, o2, o3; unpack8(sx[m], o0, o1, o2, o3);
        h2[m]              = __float2half_rn(0.05f*o0.x + 0.95f*a0.x);
        h2[(size_t)NN + m]   = __float2half_rn(0.05f*o0.y + 0.95f*a0.y);
        h2[(size_t)2*NN + m] = __float2half_rn(0.05f*o1.x + 0.95f*a1.x);
        h2[(size_t)3*NN + m] = __float2half_rn(0.05f*o1.y + 0.95f*a1.y);
        h2[(size_t)4*NN + m] = __float2half_rn(0.05f*o2.x + 0.95f*a2.x);
        h2[(size_t)5*NN + m] = __float2half_rn(0.05f*o2.y + 0.95f*a2.y);
        h2[(size_t)6*NN + m] = __float2half_rn(0.05f*o3.x + 0.95f*a3.x);
        h2[(size_t)7*NN + m] = __float2half_rn(0.05f*o3.y + 0.95f*a3.y);
    }
}

// ---------------- kernel 4: output projection via HMMA + ldmatrix ----------------
#define MMA16816(d0,d1,d2,d3,a0,a1,a2,a3,b0,b1) \
    asm volatile("mma.sync.aligned.m16n8k16.row.col.f32.f16.f16.f32 " \
        "{%0,%1,%2,%3}, {%4,%5,%6,%7}, {%8,%9}, {%0,%1,%2,%3};" \
        : "+f"(d0), "+f"(d1), "+f"(d2), "+f"(d3) \
        : "r"(a0), "r"(a1), "r"(a2), "r"(a3), "r"(b0), "r"(b1))

#define LDSM_X4(r0,r1,r2,r3,addr) \
    asm volatile("ldmatrix.sync.aligned.m8n8.x4.shared.b16 {%0,%1,%2,%3}, [%4];" \
        : "=r"(r0), "=r"(r1), "=r"(r2), "=r"(r3) : "r"(addr))

#define LDSM_X2T(r0,r1,addr) \
    asm volatile("ldmatrix.sync.aligned.m8n8.x2.trans.shared.b16 {%0,%1}, [%2];" \
        : "=r"(r0), "=r"(r1) : "r"(addr))

#define WPITCH 40    // A tile pitch (halves)
#define BPITCH 264   // B tile pitch (halves): 256 + 8 pad

__global__ void __launch_bounds__(256) k_out(float* __restrict__ out,
                                             const float* __restrict__ W1,
                                             const float* __restrict__ b1) {
    __shared__ __half sW[NC * WPITCH];        // W1 fp16, [o][c]
    __shared__ __half hT[NC * BPITCH];        // h2 tile UNtransposed, [c][n]
    __shared__ float  b1s[NC];
    int tid = threadIdx.x, lane = tid & 31, warp = tid >> 5;
    int bt = blockIdx.y;
    int b = bt / NT, t = bt - b * NT;
    int n0 = blockIdx.x * 256;

    for (int i = tid; i < NC * NC; i += 256) {
        int o = i >> 5, c = i & 31;
        sW[o * WPITCH + c] = __float2half_rn(W1[i]);
    }
    if (tid < NC) b1s[tid] = b1[tid];

    // stage h2 tile straight: hT[c][0..255] (uint4 coalesced; zero-fill OOB)
    const __half* hplane = g_h2h + (size_t)bt * NC * NN;
    {
        const uint4 z = make_uint4(0, 0, 0, 0);
        for (int i = tid; i < 32 * 32; i += 256) {       // 32 rows x 32 uint4
            int c = i >> 5, q = i & 31;
            int n = n0 + q * 8;
            uint4 u = z;
            if (n + 8 <= NN)
                u = *reinterpret_cast<const uint4*>(hplane + (size_t)c * NN + n);
            *reinterpret_cast<uint4*>(hT + c * BPITCH + q * 8) = u;
        }
    }
    __syncthreads();

    int g = lane >> 2, t4 = lane & 3;

    // A fragments via ldmatrix.x4: per (m,k) 16x16 tile of sW
    unsigned afr[2][2][4];
#pragma unroll
    for (int m = 0; m < 2; m++) {
#pragma unroll
        for (int k = 0; k < 2; k++) {
            int row = m * 16 + (lane & 15);
            int col = k * 16 + ((lane & 16) ? 8 : 0);
            unsigned addr = (unsigned)__cvta_generic_to_shared(sW + row * WPITCH + col);
            LDSM_X4(afr[m][k][0], afr[m][k][1], afr[m][k][2], afr[m][k][3], addr);
        }
    }

#pragma unroll
    for (int s = 0; s < 4; s++) {
        int nl = warp * 32 + s * 8;
        // B fragments via ldmatrix.x2.trans from row-major [k][n] tile
        unsigned bfr[2][2];
#pragma unroll
        for (int k = 0; k < 2; k++) {
            int krow = k * 16 + (lane & 15);            // lanes 0-15 supply both 8x8 matrices
            unsigned addr = (unsigned)__cvta_generic_to_shared(hT + krow * BPITCH + nl);
            LDSM_X2T(bfr[k][0], bfr[k][1], addr);
        }
#pragma unroll
        for (int m = 0; m < 2; m++) {
            float bv0 = b1s[m * 16 + g];
            float bv1 = b1s[m * 16 + g + 8];
            float d0 = bv0, d1 = bv0, d2 = bv1, d3 = bv1;
            MMA16816(d0, d1, d2, d3,
                     afr[m][0][0], afr[m][0][1], afr[m][0][2], afr[m][0][3],
                     bfr[0][0], bfr[0][1]);
            MMA16816(d0, d1, d2, d3,
                     afr[m][1][0], afr[m][1][1], afr[m][1][2], afr[m][1][3],
                     bfr[1][0], bfr[1][1]);
            int o = m * 16 + g;
            int n = n0 + nl + 2 * t4;
            if (n < NN) {
                float* op0 = out + ((size_t)(b * NC + o) * NT + t) * NN;
                float* op1 = out + ((size_t)(b * NC + o + 8) * NT + t) * NN;
                *reinterpret_cast<float2*>(op0 + n) = make_float2(d0, d1);
                *reinterpret_cast<float2*>(op1 + n) = make_float2(d2, d3);
            }
        }
    }
}

// ---------------- launch ----------------
extern "C" void kernel_launch(void* const* d_in, const int* in_sizes, int n_in,
                              void* d_out, int out_size) {
    const float* x   = (const float*)d_in[0];
    const float* adj = (const float*)d_in[1];
    const float* W1  = (const float*)d_in[2];
    const float* b1  = (const float*)d_in[3];
    const float* W2  = (const float*)d_in[4];
    const float* b2  = (const float*)d_in[5];
    const float* a   = (const float*)d_in[6];
    float* out = (float*)d_out;

    int prop_smem = 2 * NN * (int)sizeof(uint4);    // 64000 B
    cudaFuncSetAttribute(k_prop, cudaFuncAttributeMaxDynamicSharedMemorySize, prop_smem);
    int adjlr_smem = 4 * NN * (int)sizeof(float);   // 32000 B
    cudaFuncSetAttribute(k_adjlr, cudaFuncAttributeMaxDynamicSharedMemorySize, adjlr_smem);

    k_adjlr<<<ADJ_BLOCKS + LR_BLOCKS, 128, adjlr_smem>>>(adj, x, W2, b2, a);
    k_sortaval<<<NB, 1024>>>();
    {
        dim3 grid(NCHUNK, BT);
        k_prop<<<grid, PB, prop_smem>>>(x);
    }
    {
        dim3 grid((NN + 255) / 256, BT);
        k_out<<<grid, 256>>>(out, W1, b1);
    }
}